// round 1
// baseline (speedup 1.0000x reference)
#include <cuda_runtime.h>
#include <math.h>
#include <stdint.h>

// ---------------- scratch (device globals; no allocation allowed) ----------
__device__ float g_l[8*256*64*64];     // encoder feature map l
__device__ float g_t[8*128*64*64];     // res-block intermediate
__device__ float g_S[256*256];         // LISTA mutation matrix I - G/L
__device__ float g_avg[8*256];
__device__ float g_mx[8*256];
__device__ float g_catt[8*256];        // channel attention (sigmoid)
__device__ float g_s2[8*2*64*64];      // spatial-attention input
__device__ float g_satt[8*64*64];      // spatial attention (sigmoid)

static __device__ __forceinline__ float softt(float v, float la) {
    float a = fabsf(v) - la;
    a = a > 0.f ? a : 0.f;
    return copysignf(a, v);
}
static __device__ __forceinline__ float sigmoidf_(float v) {
    return 1.f / (1.f + expf(-v));
}

// ---------------- S = I - (Dict^T Dict)/L  (symmetric) ---------------------
__global__ void compute_S_kernel(const float* __restrict__ Dict,
                                 const float* __restrict__ Lp) {
    int i = blockIdx.x, j = threadIdx.x;
    float L = *Lp;
    float g = 0.f;
#pragma unroll 8
    for (int c = 0; c < 64; c++) g += Dict[c*256 + i] * Dict[c*256 + j];
    g_S[i*256 + j] = (i == j ? 1.f : 0.f) - g / L;
}

// ---------------- generic 3x3 conv, pad 1, NCHW ----------------------------
// grid: (B*16 spatial tiles of 16x16, Cout/32). 256 threads.
// thread: 8 output channels x 4 consecutive pixels.
template<bool RELU_IN, bool BIAS>
__global__ __launch_bounds__(256) void conv3x3_kernel(
    const float* __restrict__ in, const float* __restrict__ w,
    const float* __restrict__ bias, float* __restrict__ out,
    int Cin, int Cout)
{
    __shared__ float xs[16*324];   // [ic][18][18]
    __shared__ float ws[32*144];   // [oc][ic*9]

    int b    = blockIdx.x >> 4;
    int tile = blockIdx.x & 15;
    int oy0  = (tile >> 2) << 4;
    int ox0  = (tile & 3) << 4;
    int ocBase = blockIdx.y << 5;

    int tid = threadIdx.x;
    int ocg = tid >> 6;            // 0..3  -> 8 oc each
    int pxg = tid & 63;            // 0..63 -> 4 px each
    int row = pxg >> 2;
    int col = (pxg & 3) << 2;

    float acc[8][4];
#pragma unroll
    for (int o = 0; o < 8; o++)
#pragma unroll
        for (int j = 0; j < 4; j++) acc[o][j] = 0.f;

    for (int ic0 = 0; ic0 < Cin; ic0 += 16) {
        __syncthreads();
        // stage input tile (with halo, zero pad, optional relu)
        for (int i = tid; i < 16*324; i += 256) {
            int ic = i / 324;
            int rem = i - ic*324;
            int r = rem / 18, c = rem - r*18;
            int gy = oy0 - 1 + r, gx = ox0 - 1 + c;
            float v = 0.f;
            if ((unsigned)gy < 64u && (unsigned)gx < 64u) {
                v = in[(((size_t)(b*Cin + ic0 + ic))*64 + gy)*64 + gx];
                if (RELU_IN) v = fmaxf(v, 0.f);
            }
            xs[ic*324 + r*18 + c] = v;
        }
        // stage weights
        for (int i = tid; i < 32*144; i += 256) {
            int o = i / 144;
            int rem = i - o*144;        // ic*9 + k
            ws[o*144 + rem] = w[((size_t)(ocBase + o)*Cin + ic0)*9 + rem];
        }
        __syncthreads();

#pragma unroll 2
        for (int ic = 0; ic < 16; ic++) {
#pragma unroll
            for (int kh = 0; kh < 3; kh++) {
#pragma unroll
                for (int kw = 0; kw < 3; kw++) {
                    int base = ic*324 + (row+kh)*18 + col + kw;
                    float xv0 = xs[base+0];
                    float xv1 = xs[base+1];
                    float xv2 = xs[base+2];
                    float xv3 = xs[base+3];
#pragma unroll
                    for (int o = 0; o < 8; o++) {
                        float wv = ws[(ocg*8+o)*144 + ic*9 + kh*3 + kw];
                        acc[o][0] += wv*xv0;
                        acc[o][1] += wv*xv1;
                        acc[o][2] += wv*xv2;
                        acc[o][3] += wv*xv3;
                    }
                }
            }
        }
    }

#pragma unroll
    for (int o = 0; o < 8; o++) {
        int oc = ocBase + ocg*8 + o;
        float bv = BIAS ? bias[oc] : 0.f;
        float4 v = make_float4(acc[o][0]+bv, acc[o][1]+bv, acc[o][2]+bv, acc[o][3]+bv);
        *(float4*)(out + (((size_t)(b*Cout + oc)*64 + oy0 + row)*64 + ox0 + col)) = v;
    }
}

// ---------------- 1x1 conv (relu on input) + residual add into l -----------
// grid: (B*64 px-tiles of 64, 256/64 oc-tiles). 256 threads, 4x4 per thread.
__global__ __launch_bounds__(256) void conv1x1_res_kernel(
    const float* __restrict__ t, const float* __restrict__ w2,
    float* __restrict__ l)
{
    __shared__ float ws[64*64];   // [oc][k]
    __shared__ float ts[64*64];   // [k][px]

    int b   = blockIdx.x >> 6;
    int px0 = (blockIdx.x & 63) << 6;
    int ocBase = blockIdx.y << 6;
    int tid = threadIdx.x;
    int to = tid >> 4, tp = tid & 15;

    float acc[4][4];
#pragma unroll
    for (int j = 0; j < 4; j++)
#pragma unroll
        for (int i = 0; i < 4; i++) acc[j][i] = 0.f;

    for (int kc = 0; kc < 128; kc += 64) {
        __syncthreads();
        for (int i = tid; i < 4096; i += 256) {
            int o = i >> 6, k = i & 63;
            ws[o*64 + k] = w2[(ocBase + o)*128 + kc + k];
        }
        for (int i = tid; i < 4096; i += 256) {
            int k = i >> 6, p = i & 63;
            ts[k*64 + p] = fmaxf(t[((size_t)(b*128 + kc + k))*4096 + px0 + p], 0.f);
        }
        __syncthreads();
#pragma unroll 8
        for (int k = 0; k < 64; k++) {
            float4 tv = *(float4*)&ts[k*64 + tp*4];
#pragma unroll
            for (int j = 0; j < 4; j++) {
                float wv = ws[(to*4+j)*64 + k];
                acc[j][0] += wv*tv.x;
                acc[j][1] += wv*tv.y;
                acc[j][2] += wv*tv.z;
                acc[j][3] += wv*tv.w;
            }
        }
    }

#pragma unroll
    for (int j = 0; j < 4; j++) {
        size_t oi = ((size_t)(b*256 + ocBase + to*4 + j))*4096 + px0 + tp*4;
        float4 lv = *(float4*)(l + oi);
        lv.x += acc[j][0]; lv.y += acc[j][1]; lv.z += acc[j][2]; lv.w += acc[j][3];
        *(float4*)(l + oi) = lv;
    }
}

// ---------------- channel attention: pooled reductions ---------------------
__global__ void pool_kernel() {
    int bc = blockIdx.x;             // b*256 + ch
    const float* p = g_l + (size_t)bc*4096;
    int tid = threadIdx.x;
    float s = 0.f, m = -3.402823466e38f;
    for (int i = tid; i < 4096; i += 256) {
        float v = p[i];
        s += v; m = fmaxf(m, v);
    }
    __shared__ float ss[256], smx[256];
    ss[tid] = s; smx[tid] = m;
    __syncthreads();
    for (int st = 128; st > 0; st >>= 1) {
        if (tid < st) { ss[tid] += ss[tid+st]; smx[tid] = fmaxf(smx[tid], smx[tid+st]); }
        __syncthreads();
    }
    if (tid == 0) { g_avg[bc] = ss[0] * (1.f/4096.f); g_mx[bc] = smx[0]; }
}

// ---------------- channel attention MLP (tiny) -----------------------------
__global__ void camlp_kernel(const float* __restrict__ w1,
                             const float* __restrict__ w2) {
    int b = blockIdx.x;
    int tid = threadIdx.x;
    __shared__ float av[256], mv[256], ha[16], hm[16];
    av[tid] = g_avg[b*256 + tid];
    mv[tid] = g_mx[b*256 + tid];
    __syncthreads();
    if (tid < 16) {
        float sa = 0.f, sm_ = 0.f;
        for (int c = 0; c < 256; c++) {
            float wv = w1[tid*256 + c];
            sa  += av[c]*wv;
            sm_ += mv[c]*wv;
        }
        ha[tid] = fmaxf(sa, 0.f);
        hm[tid] = fmaxf(sm_, 0.f);
    }
    __syncthreads();
    float oa = 0.f, om = 0.f;
#pragma unroll
    for (int j = 0; j < 16; j++) {
        float wv = w2[tid*16 + j];
        oa += ha[j]*wv;
        om += hm[j]*wv;
    }
    g_catt[b*256 + tid] = sigmoidf_(oa + om);
}

// ---------------- spatial stats of channel-scaled l ------------------------
__global__ void spatial_stats_kernel() {
    int b   = blockIdx.x >> 4;
    int px  = ((blockIdx.x & 15) << 8) + threadIdx.x;
    __shared__ float ca[256];
    ca[threadIdx.x] = g_catt[b*256 + threadIdx.x];
    __syncthreads();
    float s = 0.f, m = -3.402823466e38f;
    for (int ch = 0; ch < 256; ch++) {
        float v = g_l[((size_t)(b*256 + ch))*4096 + px] * ca[ch];
        s += v; m = fmaxf(m, v);
    }
    g_s2[((size_t)(b*2 + 0))*4096 + px] = s * (1.f/256.f);
    g_s2[((size_t)(b*2 + 1))*4096 + px] = m;
}

// ---------------- spatial attention conv (2->1, 3x3, pad1) -----------------
__global__ void saconv_kernel(const float* __restrict__ saw) {
    int b  = blockIdx.x >> 4;
    int px = ((blockIdx.x & 15) << 8) + threadIdx.x;
    int py = px >> 6, pxx = px & 63;
    __shared__ float w[18];
    if (threadIdx.x < 18) w[threadIdx.x] = saw[threadIdx.x];
    __syncthreads();
    float a = 0.f;
#pragma unroll
    for (int ch = 0; ch < 2; ch++)
#pragma unroll
        for (int kh = 0; kh < 3; kh++)
#pragma unroll
            for (int kw = 0; kw < 3; kw++) {
                int gy = py - 1 + kh, gx = pxx - 1 + kw;
                if ((unsigned)gy < 64u && (unsigned)gx < 64u)
                    a += g_s2[((size_t)(b*2 + ch))*4096 + gy*64 + gx] * w[ch*9 + kh*3 + kw];
            }
    g_satt[b*4096 + px] = sigmoidf_(a);
}

// ---------------- LISTA persistent kernel ----------------------------------
// 32 pixels per block resident in smem across all iterations.
// thread: n0 = tid&127 handles cols {n0, n0+128}; pg = tid>>7 handles 16 px.
#define LISTA_SMEM ((3*32*257 + 32*65)*4)

__global__ __launch_bounds__(256, 1) void lista_kernel(
    const float* __restrict__ x, const float* __restrict__ Dict,
    const float* __restrict__ Lp, const int* __restrict__ iterp,
    float* __restrict__ zOut, float* __restrict__ xrOut)
{
    extern __shared__ float smem[];
    float* zs  = smem;                 // [32][257]
    float* yl  = smem + 32*257;        // [32][257]
    float* lam = smem + 2*32*257;      // [32][257]
    float* xsh = smem + 3*32*257;      // [32][65]

    int tid = threadIdx.x;
    int gp0 = blockIdx.x * 32;
    int b   = gp0 >> 12;
    int px0 = gp0 & 4095;
    float invL = 1.f / *Lp;
    int iters = *iterp;

    // stage x pixels [32][64] (coalesced in p, padded pitch 65)
    for (int i = tid; i < 2048; i += 256) {
        int c = i >> 5, p = i & 31;
        xsh[p*65 + c] = x[((size_t)(b*64 + c))*4096 + px0 + p];
    }
    // stage per-position thresholds lam = l*catt*satt/L
    for (int i = tid; i < 8192; i += 256) {
        int n = i >> 5, p = i & 31;
        float lv = g_l[((size_t)(b*256 + n))*4096 + px0 + p];
        lam[p*257 + n] = lv * g_catt[b*256 + n] * g_satt[b*4096 + px0 + p] * invL;
    }
    __syncthreads();

    int n0 = tid & 127;
    int pg = tid >> 7;

    // y = x @ Dict ; yl = y/L ; z0 = soft(y, lam)
    {
        float acc0[16], acc1[16];
#pragma unroll
        for (int p = 0; p < 16; p++) { acc0[p] = 0.f; acc1[p] = 0.f; }
        for (int c = 0; c < 64; c++) {
            float d0 = Dict[c*256 + n0];
            float d1 = Dict[c*256 + n0 + 128];
#pragma unroll
            for (int p = 0; p < 16; p++) {
                float xv = xsh[(pg*16 + p)*65 + c];
                acc0[p] += xv*d0;
                acc1[p] += xv*d1;
            }
        }
#pragma unroll
        for (int p = 0; p < 16; p++) {
            int idx = (pg*16 + p)*257 + n0;
            yl[idx]       = acc0[p]*invL;
            zs[idx]       = softt(acc0[p], lam[idx]);
            yl[idx + 128] = acc1[p]*invL;
            zs[idx + 128] = softt(acc1[p], lam[idx + 128]);
        }
    }
    __syncthreads();

    // main fixed-point loop: z = soft(z @ S + y/L, lam)
    for (int it = 0; it < iters; it++) {
        float acc0[16], acc1[16];
#pragma unroll
        for (int p = 0; p < 16; p++) { acc0[p] = 0.f; acc1[p] = 0.f; }

        float sb0[4], sb1[4];
#pragma unroll
        for (int j = 0; j < 4; j++) {
            sb0[j] = g_S[j*256 + n0];
            sb1[j] = g_S[j*256 + n0 + 128];
        }
        for (int k4 = 0; k4 < 256; k4 += 4) {
            float sc0[4], sc1[4];
#pragma unroll
            for (int j = 0; j < 4; j++) { sc0[j] = sb0[j]; sc1[j] = sb1[j]; }
            if (k4 + 4 < 256) {
#pragma unroll
                for (int j = 0; j < 4; j++) {
                    sb0[j] = g_S[(k4 + 4 + j)*256 + n0];
                    sb1[j] = g_S[(k4 + 4 + j)*256 + n0 + 128];
                }
            }
#pragma unroll
            for (int j = 0; j < 4; j++) {
#pragma unroll
                for (int p = 0; p < 16; p++) {
                    float zv = zs[(pg*16 + p)*257 + k4 + j];
                    acc0[p] += zv*sc0[j];
                    acc1[p] += zv*sc1[j];
                }
            }
        }
        __syncthreads();
#pragma unroll
        for (int p = 0; p < 16; p++) {
            int idx = (pg*16 + p)*257 + n0;
            zs[idx]       = softt(acc0[p] + yl[idx],       lam[idx]);
            zs[idx + 128] = softt(acc1[p] + yl[idx + 128], lam[idx + 128]);
        }
        __syncthreads();
    }

    // write z (coalesced: thread = (p, n-group))
    {
        int p = tid & 31, ng = tid >> 5;
        for (int n = ng*32; n < ng*32 + 32; n++)
            zOut[((size_t)(b*256 + n))*4096 + px0 + p] = zs[p*257 + n];
    }
    __syncthreads();

    // reuse yl+lam region (16448 floats) for Dict (16384 floats)
    float* dsh = yl;
    for (int i = tid; i < 16384; i += 256) dsh[i] = Dict[i];
    __syncthreads();

    // x_recon = z @ Dict^T
    {
        int p = tid & 31, cg = tid >> 5;
        float acc[8];
#pragma unroll
        for (int j = 0; j < 8; j++) acc[j] = 0.f;
        for (int a = 0; a < 256; a++) {
            float zv = zs[p*257 + a];
#pragma unroll
            for (int j = 0; j < 8; j++)
                acc[j] += zv * dsh[(cg*8 + j)*256 + a];
        }
#pragma unroll
        for (int j = 0; j < 8; j++)
            xrOut[((size_t)(b*64 + cg*8 + j))*4096 + px0 + p] = acc[j];
    }
}

// ---------------- launch ----------------------------------------------------
extern "C" void kernel_launch(void* const* d_in, const int* in_sizes, int n_in,
                              void* d_out, int out_size)
{
    const float* x      = (const float*)d_in[0];
    const float* conv_w = (const float*)d_in[1];
    const float* conv_b = (const float*)d_in[2];
    const float* r1w1   = (const float*)d_in[3];
    const float* r1w2   = (const float*)d_in[4];
    const float* r2w1   = (const float*)d_in[5];
    const float* r2w2   = (const float*)d_in[6];
    const float* caw1   = (const float*)d_in[7];
    const float* caw2   = (const float*)d_in[8];
    const float* saw    = (const float*)d_in[9];
    const float* Dict   = (const float*)d_in[10];
    const float* Lp     = (const float*)d_in[11];
    const int*   itp    = (const int*)d_in[12];

    float* out   = (float*)d_out;
    float* zOut  = out;
    float* xrOut = out + (size_t)8*256*4096;
    float* dOut  = xrOut + (size_t)8*64*4096;

    float *lp, *tp;
    cudaGetSymbolAddress((void**)&lp, g_l);
    cudaGetSymbolAddress((void**)&tp, g_t);

    compute_S_kernel<<<256, 256>>>(Dict, Lp);

    conv3x3_kernel<false, true><<<dim3(128, 8), 256>>>(x, conv_w, conv_b, lp, 64, 256);

    conv3x3_kernel<true, false><<<dim3(128, 4), 256>>>(lp, r1w1, nullptr, tp, 256, 128);
    conv1x1_res_kernel<<<dim3(512, 4), 256>>>(tp, r1w2, lp);

    conv3x3_kernel<true, false><<<dim3(128, 4), 256>>>(lp, r2w1, nullptr, tp, 256, 128);
    conv1x1_res_kernel<<<dim3(512, 4), 256>>>(tp, r2w2, lp);

    pool_kernel<<<2048, 256>>>();
    camlp_kernel<<<8, 256>>>(caw1, caw2);
    spatial_stats_kernel<<<128, 256>>>();
    saconv_kernel<<<128, 256>>>(saw);

    cudaFuncSetAttribute(lista_kernel, cudaFuncAttributeMaxDynamicSharedMemorySize, LISTA_SMEM);
    lista_kernel<<<1024, 256, LISTA_SMEM>>>(x, Dict, Lp, itp, zOut, xrOut);

    cudaMemcpyAsync(dOut, Dict, (size_t)64*256*sizeof(float), cudaMemcpyDeviceToDevice);
}

// round 2
// speedup vs baseline: 1.4165x; 1.4165x over previous
#include <cuda_runtime.h>
#include <math.h>
#include <stdint.h>

// ---------------- scratch (device globals; no allocation allowed) ----------
__device__ float g_l[8*256*64*64];     // encoder feature map l
__device__ float g_t[8*128*64*64];     // res-block intermediate
__device__ float g_S[256*256];         // LISTA matrix I - G/L (tf32-rounded)
__device__ float g_avg[8*256];
__device__ float g_mx[8*256];
__device__ float g_catt[8*256];        // channel attention (sigmoid)
__device__ float g_s2[8*2*64*64];      // spatial-attention input
__device__ float g_satt[8*64*64];      // spatial attention (sigmoid)

static __device__ __forceinline__ float softt(float v, float la) {
    float a = fabsf(v) - la;
    a = a > 0.f ? a : 0.f;
    return copysignf(a, v);
}
static __device__ __forceinline__ float sigmoidf_(float v) {
    return 1.f / (1.f + expf(-v));
}
static __device__ __forceinline__ uint32_t f2tf32(float f) {
    uint32_t r;
    asm("cvt.rna.tf32.f32 %0, %1;" : "=r"(r) : "f"(f));
    return r;
}
static __device__ __forceinline__ void mma_tf32(float* c, const uint32_t* a,
                                                uint32_t b0, uint32_t b1) {
    asm volatile(
        "mma.sync.aligned.m16n8k8.row.col.f32.tf32.tf32.f32 "
        "{%0,%1,%2,%3}, {%4,%5,%6,%7}, {%8,%9}, {%0,%1,%2,%3};\n"
        : "+f"(c[0]), "+f"(c[1]), "+f"(c[2]), "+f"(c[3])
        : "r"(a[0]), "r"(a[1]), "r"(a[2]), "r"(a[3]), "r"(b0), "r"(b1));
}

// ---------------- S = I - (Dict^T Dict)/L  (symmetric, tf32-rounded) -------
__global__ void compute_S_kernel(const float* __restrict__ Dict,
                                 const float* __restrict__ Lp) {
    int i = blockIdx.x, j = threadIdx.x;
    float L = *Lp;
    float g = 0.f;
#pragma unroll 8
    for (int c = 0; c < 64; c++) g += Dict[c*256 + i] * Dict[c*256 + j];
    float v = (i == j ? 1.f : 0.f) - g / L;
    g_S[i*256 + j] = __uint_as_float(f2tf32(v));
}

// ---------------- generic 3x3 conv, pad 1, NCHW ----------------------------
template<bool RELU_IN, bool BIAS>
__global__ __launch_bounds__(256) void conv3x3_kernel(
    const float* __restrict__ in, const float* __restrict__ w,
    const float* __restrict__ bias, float* __restrict__ out,
    int Cin, int Cout)
{
    __shared__ float xs[16*324];   // [ic][18][18]
    __shared__ float ws[32*144];   // [oc][ic*9]

    int b    = blockIdx.x >> 4;
    int tile = blockIdx.x & 15;
    int oy0  = (tile >> 2) << 4;
    int ox0  = (tile & 3) << 4;
    int ocBase = blockIdx.y << 5;

    int tid = threadIdx.x;
    int ocg = tid >> 6;
    int pxg = tid & 63;
    int row = pxg >> 2;
    int col = (pxg & 3) << 2;

    float acc[8][4];
#pragma unroll
    for (int o = 0; o < 8; o++)
#pragma unroll
        for (int j = 0; j < 4; j++) acc[o][j] = 0.f;

    for (int ic0 = 0; ic0 < Cin; ic0 += 16) {
        __syncthreads();
        for (int i = tid; i < 16*324; i += 256) {
            int ic = i / 324;
            int rem = i - ic*324;
            int r = rem / 18, c = rem - r*18;
            int gy = oy0 - 1 + r, gx = ox0 - 1 + c;
            float v = 0.f;
            if ((unsigned)gy < 64u && (unsigned)gx < 64u) {
                v = in[(((size_t)(b*Cin + ic0 + ic))*64 + gy)*64 + gx];
                if (RELU_IN) v = fmaxf(v, 0.f);
            }
            xs[ic*324 + r*18 + c] = v;
        }
        for (int i = tid; i < 32*144; i += 256) {
            int o = i / 144;
            int rem = i - o*144;
            ws[o*144 + rem] = w[((size_t)(ocBase + o)*Cin + ic0)*9 + rem];
        }
        __syncthreads();

#pragma unroll 2
        for (int ic = 0; ic < 16; ic++) {
#pragma unroll
            for (int kh = 0; kh < 3; kh++) {
#pragma unroll
                for (int kw = 0; kw < 3; kw++) {
                    int base = ic*324 + (row+kh)*18 + col + kw;
                    float xv0 = xs[base+0];
                    float xv1 = xs[base+1];
                    float xv2 = xs[base+2];
                    float xv3 = xs[base+3];
#pragma unroll
                    for (int o = 0; o < 8; o++) {
                        float wv = ws[(ocg*8+o)*144 + ic*9 + kh*3 + kw];
                        acc[o][0] += wv*xv0;
                        acc[o][1] += wv*xv1;
                        acc[o][2] += wv*xv2;
                        acc[o][3] += wv*xv3;
                    }
                }
            }
        }
    }

#pragma unroll
    for (int o = 0; o < 8; o++) {
        int oc = ocBase + ocg*8 + o;
        float bv = BIAS ? bias[oc] : 0.f;
        float4 v = make_float4(acc[o][0]+bv, acc[o][1]+bv, acc[o][2]+bv, acc[o][3]+bv);
        *(float4*)(out + (((size_t)(b*Cout + oc)*64 + oy0 + row)*64 + ox0 + col)) = v;
    }
}

// ---------------- 1x1 conv (relu on input) + residual add into l -----------
__global__ __launch_bounds__(256) void conv1x1_res_kernel(
    const float* __restrict__ t, const float* __restrict__ w2,
    float* __restrict__ l)
{
    __shared__ float ws[64*64];
    __shared__ float ts[64*64];

    int b   = blockIdx.x >> 6;
    int px0 = (blockIdx.x & 63) << 6;
    int ocBase = blockIdx.y << 6;
    int tid = threadIdx.x;
    int to = tid >> 4, tp = tid & 15;

    float acc[4][4];
#pragma unroll
    for (int j = 0; j < 4; j++)
#pragma unroll
        for (int i = 0; i < 4; i++) acc[j][i] = 0.f;

    for (int kc = 0; kc < 128; kc += 64) {
        __syncthreads();
        for (int i = tid; i < 4096; i += 256) {
            int o = i >> 6, k = i & 63;
            ws[o*64 + k] = w2[(ocBase + o)*128 + kc + k];
        }
        for (int i = tid; i < 4096; i += 256) {
            int k = i >> 6, p = i & 63;
            ts[k*64 + p] = fmaxf(t[((size_t)(b*128 + kc + k))*4096 + px0 + p], 0.f);
        }
        __syncthreads();
#pragma unroll 8
        for (int k = 0; k < 64; k++) {
            float4 tv = *(float4*)&ts[k*64 + tp*4];
#pragma unroll
            for (int j = 0; j < 4; j++) {
                float wv = ws[(to*4+j)*64 + k];
                acc[j][0] += wv*tv.x;
                acc[j][1] += wv*tv.y;
                acc[j][2] += wv*tv.z;
                acc[j][3] += wv*tv.w;
            }
        }
    }

#pragma unroll
    for (int j = 0; j < 4; j++) {
        size_t oi = ((size_t)(b*256 + ocBase + to*4 + j))*4096 + px0 + tp*4;
        float4 lv = *(float4*)(l + oi);
        lv.x += acc[j][0]; lv.y += acc[j][1]; lv.z += acc[j][2]; lv.w += acc[j][3];
        *(float4*)(l + oi) = lv;
    }
}

// ---------------- channel attention: pooled reductions ---------------------
__global__ void pool_kernel() {
    int bc = blockIdx.x;
    const float* p = g_l + (size_t)bc*4096;
    int tid = threadIdx.x;
    float s = 0.f, m = -3.402823466e38f;
    for (int i = tid; i < 4096; i += 256) {
        float v = p[i];
        s += v; m = fmaxf(m, v);
    }
    __shared__ float ss[256], smx[256];
    ss[tid] = s; smx[tid] = m;
    __syncthreads();
    for (int st = 128; st > 0; st >>= 1) {
        if (tid < st) { ss[tid] += ss[tid+st]; smx[tid] = fmaxf(smx[tid], smx[tid+st]); }
        __syncthreads();
    }
    if (tid == 0) { g_avg[bc] = ss[0] * (1.f/4096.f); g_mx[bc] = smx[0]; }
}

// ---------------- channel attention MLP (tiny) -----------------------------
__global__ void camlp_kernel(const float* __restrict__ w1,
                             const float* __restrict__ w2) {
    int b = blockIdx.x;
    int tid = threadIdx.x;
    __shared__ float av[256], mv[256], ha[16], hm[16];
    av[tid] = g_avg[b*256 + tid];
    mv[tid] = g_mx[b*256 + tid];
    __syncthreads();
    if (tid < 16) {
        float sa = 0.f, sm_ = 0.f;
        for (int c = 0; c < 256; c++) {
            float wv = w1[tid*256 + c];
            sa  += av[c]*wv;
            sm_ += mv[c]*wv;
        }
        ha[tid] = fmaxf(sa, 0.f);
        hm[tid] = fmaxf(sm_, 0.f);
    }
    __syncthreads();
    float oa = 0.f, om = 0.f;
#pragma unroll
    for (int j = 0; j < 16; j++) {
        float wv = w2[tid*16 + j];
        oa += ha[j]*wv;
        om += hm[j]*wv;
    }
    g_catt[b*256 + tid] = sigmoidf_(oa + om);
}

// ---------------- spatial stats of channel-scaled l ------------------------
__global__ void spatial_stats_kernel() {
    int b   = blockIdx.x >> 4;
    int px  = ((blockIdx.x & 15) << 8) + threadIdx.x;
    __shared__ float ca[256];
    ca[threadIdx.x] = g_catt[b*256 + threadIdx.x];
    __syncthreads();
    float s = 0.f, m = -3.402823466e38f;
    for (int ch = 0; ch < 256; ch++) {
        float v = g_l[((size_t)(b*256 + ch))*4096 + px] * ca[ch];
        s += v; m = fmaxf(m, v);
    }
    g_s2[((size_t)(b*2 + 0))*4096 + px] = s * (1.f/256.f);
    g_s2[((size_t)(b*2 + 1))*4096 + px] = m;
}

// ---------------- spatial attention conv (2->1, 3x3, pad1) -----------------
__global__ void saconv_kernel(const float* __restrict__ saw) {
    int b  = blockIdx.x >> 4;
    int px = ((blockIdx.x & 15) << 8) + threadIdx.x;
    int py = px >> 6, pxx = px & 63;
    __shared__ float w[18];
    if (threadIdx.x < 18) w[threadIdx.x] = saw[threadIdx.x];
    __syncthreads();
    float a = 0.f;
#pragma unroll
    for (int ch = 0; ch < 2; ch++)
#pragma unroll
        for (int kh = 0; kh < 3; kh++)
#pragma unroll
            for (int kw = 0; kw < 3; kw++) {
                int gy = py - 1 + kh, gx = pxx - 1 + kw;
                if ((unsigned)gy < 64u && (unsigned)gx < 64u)
                    a += g_s2[((size_t)(b*2 + ch))*4096 + gy*64 + gx] * w[ch*9 + kh*3 + kw];
            }
    g_satt[b*4096 + px] = sigmoidf_(a);
}

// ---------------- LISTA persistent tensor-core kernel ----------------------
// 64 pixels per CTA, z/yl/lam resident in smem; S streamed through smem.
// 8 warps: 2 along M (32 px) x 4 along N (64 atoms). mma.sync m16n8k8 tf32.
#define ZS_OFF   0
#define YL_OFF   16640
#define LAM_OFF  33280
#define SS_OFF   49920              // 2 x 2304 (double-buffered [n][9])
#define XSH_OFF  49920              // aliases SS (init phase only)
#define DSH_OFF  16640              // aliases YL+LAM (epilogue only)
#define LISTA_SMEM ((49920 + 2*2304) * 4)

__global__ __launch_bounds__(256, 1) void lista_kernel(
    const float* __restrict__ x, const float* __restrict__ Dict,
    const float* __restrict__ Lp, const int* __restrict__ iterp,
    float* __restrict__ zOut, float* __restrict__ xrOut)
{
    extern __shared__ __align__(16) float smem[];
    float* zs  = smem + ZS_OFF;     // [64][260]
    float* yl  = smem + YL_OFF;     // [64][260]
    float* lam = smem + LAM_OFF;    // [64][260]
    float* sS  = smem + SS_OFF;     // [2][256][9]
    float* xsh = smem + XSH_OFF;    // [64][68]

    int tid = threadIdx.x;
    int gp0 = blockIdx.x * 64;
    int b   = gp0 >> 12;
    int px0 = gp0 & 4095;
    float invL = 1.f / *Lp;
    int iters = *iterp;

    // stage x pixels [64][68]
    for (int i = tid; i < 4096; i += 256) {
        int c = i >> 6, p = i & 63;
        xsh[p*68 + c] = x[((size_t)(b*64 + c))*4096 + px0 + p];
    }
    // stage thresholds lam = l*catt*satt/L
    for (int i = tid; i < 16384; i += 256) {
        int n = i >> 6, p = i & 63;
        float lv = g_l[((size_t)(b*256 + n))*4096 + px0 + p];
        lam[p*260 + n] = lv * g_catt[b*256 + n] * g_satt[b*4096 + px0 + p] * invL;
    }
    __syncthreads();

    // y = x @ Dict ; yl = y/L ; z0 = soft(y, lam)   (scalar, small)
    {
        int n0 = tid & 63;
        int pg = tid >> 6;            // 4 groups of 16 px
        float acc[16][4];
#pragma unroll
        for (int p = 0; p < 16; p++)
#pragma unroll
            for (int j = 0; j < 4; j++) acc[p][j] = 0.f;
        for (int c = 0; c < 64; c++) {
            float d0 = Dict[c*256 + n0];
            float d1 = Dict[c*256 + n0 + 64];
            float d2 = Dict[c*256 + n0 + 128];
            float d3 = Dict[c*256 + n0 + 192];
#pragma unroll
            for (int p = 0; p < 16; p++) {
                float xv = xsh[(pg*16 + p)*68 + c];
                acc[p][0] += xv*d0;
                acc[p][1] += xv*d1;
                acc[p][2] += xv*d2;
                acc[p][3] += xv*d3;
            }
        }
#pragma unroll
        for (int p = 0; p < 16; p++)
#pragma unroll
            for (int j = 0; j < 4; j++) {
                int idx = (pg*16 + p)*260 + n0 + 64*j;
                yl[idx] = acc[p][j]*invL;
                zs[idx] = softt(acc[p][j], lam[idx]);
            }
    }
    // NOTE: xsh dead from here; sS aliases it.

    const int lane = tid & 31;
    const int warp = tid >> 5;
    const int wm   = warp >> 2;       // 0..1
    const int wn   = warp & 3;        // 0..3
    const int g    = lane >> 2;
    const int t    = lane & 3;
    const int mBase = wm*32;
    const int nBase = wn*64;

    // preload S chunk 0 (rows 0..7, column tid)
    float rS[8];
#pragma unroll
    for (int k = 0; k < 8; k++) rS[k] = g_S[k*256 + tid];

    for (int it = 0; it < iters; it++) {
        float acc[2][8][4];
#pragma unroll
        for (int am = 0; am < 2; am++)
#pragma unroll
            for (int nt = 0; nt < 8; nt++)
#pragma unroll
                for (int j = 0; j < 4; j++) acc[am][nt][j] = 0.f;

        // store chunk 0 into buffer 0
#pragma unroll
        for (int k = 0; k < 8; k++) sS[tid*9 + k] = rS[k];

        for (int kc = 0; kc < 32; kc++) {
            if (kc + 1 < 32) {
#pragma unroll
                for (int k = 0; k < 8; k++)
                    rS[k] = g_S[((kc+1)*8 + k)*256 + tid];
            }
            __syncthreads();   // buffer (kc&1) ready; prev reads of other buf done

            int k0 = kc*8;
            uint32_t a[2][4];
#pragma unroll
            for (int am = 0; am < 2; am++) {
                int row = mBase + am*16 + g;
                a[am][0] = f2tf32(zs[row*260 + k0 + t]);
                a[am][1] = f2tf32(zs[(row+8)*260 + k0 + t]);
                a[am][2] = f2tf32(zs[row*260 + k0 + t + 4]);
                a[am][3] = f2tf32(zs[(row+8)*260 + k0 + t + 4]);
            }
            const float* sb = sS + (kc & 1)*2304;
#pragma unroll
            for (int nt = 0; nt < 8; nt++) {
                int nn = nBase + nt*8 + g;
                uint32_t b0 = __float_as_uint(sb[nn*9 + t]);
                uint32_t b1 = __float_as_uint(sb[nn*9 + t + 4]);
                mma_tf32(acc[0][nt], a[0], b0, b1);
                mma_tf32(acc[1][nt], a[1], b0, b1);
            }
            if (kc + 1 < 32) {
#pragma unroll
                for (int k = 0; k < 8; k++)
                    sS[((kc+1)&1)*2304 + tid*9 + k] = rS[k];
            }
        }

        // preload chunk 0 for next iteration (hide latency under epilogue)
        if (it + 1 < iters) {
#pragma unroll
            for (int k = 0; k < 8; k++) rS[k] = g_S[k*256 + tid];
        }
        __syncthreads();   // all A-frag reads of zs complete

        // epilogue: z = soft(acc + y/L, lam), write back to zs
#pragma unroll
        for (int am = 0; am < 2; am++) {
#pragma unroll
            for (int nt = 0; nt < 8; nt++) {
                int row = mBase + am*16 + g;
                int col = nBase + nt*8 + 2*t;
                int i0 = row*260 + col;
                int i1 = (row+8)*260 + col;
                zs[i0]   = softt(acc[am][nt][0] + yl[i0],   lam[i0]);
                zs[i0+1] = softt(acc[am][nt][1] + yl[i0+1], lam[i0+1]);
                zs[i1]   = softt(acc[am][nt][2] + yl[i1],   lam[i1]);
                zs[i1+1] = softt(acc[am][nt][3] + yl[i1+1], lam[i1+1]);
            }
        }
        __syncthreads();
    }

    // write z out (coalesced over px)
    for (int i = tid; i < 16384; i += 256) {
        int n = i >> 6, p = i & 63;
        zOut[((size_t)(b*256 + n))*4096 + px0 + p] = zs[p*260 + n];
    }
    __syncthreads();

    // stage Dict transposed into dsh[a][68] (aliases yl/lam region)
    float* dsh = smem + DSH_OFF;
    for (int i = tid; i < 16384; i += 256) {
        int c = i >> 8, a = i & 255;
        dsh[a*68 + c] = Dict[c*256 + a];
    }
    __syncthreads();

    // x_recon = z @ Dict^T
    {
        int p = tid & 63, cg = tid >> 6;   // 4 groups x 16 channels
        float acc[16];
#pragma unroll
        for (int j = 0; j < 16; j++) acc[j] = 0.f;
        for (int a = 0; a < 256; a++) {
            float zv = zs[p*260 + a];
            const float4* dr = (const float4*)&dsh[a*68 + cg*16];
            float4 d0 = dr[0], d1 = dr[1], d2 = dr[2], d3 = dr[3];
            acc[0]  += zv*d0.x; acc[1]  += zv*d0.y; acc[2]  += zv*d0.z; acc[3]  += zv*d0.w;
            acc[4]  += zv*d1.x; acc[5]  += zv*d1.y; acc[6]  += zv*d1.z; acc[7]  += zv*d1.w;
            acc[8]  += zv*d2.x; acc[9]  += zv*d2.y; acc[10] += zv*d2.z; acc[11] += zv*d2.w;
            acc[12] += zv*d3.x; acc[13] += zv*d3.y; acc[14] += zv*d3.z; acc[15] += zv*d3.w;
        }
#pragma unroll
        for (int j = 0; j < 16; j++)
            xrOut[((size_t)(b*64 + cg*16 + j))*4096 + px0 + p] = acc[j];
    }
}

// ---------------- launch ----------------------------------------------------
extern "C" void kernel_launch(void* const* d_in, const int* in_sizes, int n_in,
                              void* d_out, int out_size)
{
    const float* x      = (const float*)d_in[0];
    const float* conv_w = (const float*)d_in[1];
    const float* conv_b = (const float*)d_in[2];
    const float* r1w1   = (const float*)d_in[3];
    const float* r1w2   = (const float*)d_in[4];
    const float* r2w1   = (const float*)d_in[5];
    const float* r2w2   = (const float*)d_in[6];
    const float* caw1   = (const float*)d_in[7];
    const float* caw2   = (const float*)d_in[8];
    const float* saw    = (const float*)d_in[9];
    const float* Dict   = (const float*)d_in[10];
    const float* Lp     = (const float*)d_in[11];
    const int*   itp    = (const int*)d_in[12];

    float* out   = (float*)d_out;
    float* zOut  = out;
    float* xrOut = out + (size_t)8*256*4096;
    float* dOut  = xrOut + (size_t)8*64*4096;

    float *lp, *tp;
    cudaGetSymbolAddress((void**)&lp, g_l);
    cudaGetSymbolAddress((void**)&tp, g_t);

    compute_S_kernel<<<256, 256>>>(Dict, Lp);

    conv3x3_kernel<false, true><<<dim3(128, 8), 256>>>(x, conv_w, conv_b, lp, 64, 256);

    conv3x3_kernel<true, false><<<dim3(128, 4), 256>>>(lp, r1w1, nullptr, tp, 256, 128);
    conv1x1_res_kernel<<<dim3(512, 4), 256>>>(tp, r1w2, lp);

    conv3x3_kernel<true, false><<<dim3(128, 4), 256>>>(lp, r2w1, nullptr, tp, 256, 128);
    conv1x1_res_kernel<<<dim3(512, 4), 256>>>(tp, r2w2, lp);

    pool_kernel<<<2048, 256>>>();
    camlp_kernel<<<8, 256>>>(caw1, caw2);
    spatial_stats_kernel<<<128, 256>>>();
    saconv_kernel<<<128, 256>>>(saw);

    cudaFuncSetAttribute(lista_kernel, cudaFuncAttributeMaxDynamicSharedMemorySize, LISTA_SMEM);
    lista_kernel<<<512, 256, LISTA_SMEM>>>(x, Dict, Lp, itp, zOut, xrOut);

    cudaMemcpyAsync(dOut, Dict, (size_t)64*256*sizeof(float), cudaMemcpyDeviceToDevice);
}

// round 7
// speedup vs baseline: 1.9581x; 1.3824x over previous
#include <cuda_runtime.h>
#include <math.h>
#include <stdint.h>

// ---------------- scratch (device globals; no allocation allowed) ----------
__device__ float g_l[8*256*64*64];     // encoder feature map l
__device__ float g_t[8*128*64*64];     // res-block intermediate
__device__ float g_S[256*256];         // LISTA matrix I - G/L (tf32-rounded)
__device__ float g_avg[8*256];
__device__ float g_mx[8*256];
__device__ float g_catt[8*256];        // channel attention (sigmoid)
__device__ float g_s2[8*2*64*64];      // spatial-attention input
__device__ float g_satt[8*64*64];      // spatial attention (sigmoid)

static __device__ __forceinline__ float softt(float v, float la) {
    float a = fabsf(v) - la;
    a = a > 0.f ? a : 0.f;
    return copysignf(a, v);
}
static __device__ __forceinline__ float sigmoidf_(float v) {
    return 1.f / (1.f + expf(-v));
}
static __device__ __forceinline__ uint32_t f2tf32(float f) {
    uint32_t r;
    asm("cvt.rna.tf32.f32 %0, %1;" : "=r"(r) : "f"(f));
    return r;
}
static __device__ __forceinline__ void mma_tf32(float* c, const uint32_t* a,
                                                uint32_t b0, uint32_t b1) {
    asm volatile(
        "mma.sync.aligned.m16n8k8.row.col.f32.tf32.tf32.f32 "
        "{%0,%1,%2,%3}, {%4,%5,%6,%7}, {%8,%9}, {%0,%1,%2,%3};\n"
        : "+f"(c[0]), "+f"(c[1]), "+f"(c[2]), "+f"(c[3])
        : "r"(a[0]), "r"(a[1]), "r"(a[2]), "r"(a[3]), "r"(b0), "r"(b1));
}

// ---------------- S = I - (Dict^T Dict)/L  (symmetric, tf32-rounded) -------
__global__ void compute_S_kernel(const float* __restrict__ Dict,
                                 const float* __restrict__ Lp) {
    int i = blockIdx.x, j = threadIdx.x;
    float L = *Lp;
    float g = 0.f;
#pragma unroll 8
    for (int c = 0; c < 64; c++) g += Dict[c*256 + i] * Dict[c*256 + j];
    float v = (i == j ? 1.f : 0.f) - g / L;
    g_S[i*256 + j] = __uint_as_float(f2tf32(v));
}

// ---------------- 3x3 conv, pad 1, NCHW, tensor-core tf32 ------------------
// 16x16 spatial tile (N=256 px), 64 oc (M), implicit GEMM: 9 shifted K=CIN
// GEMMs in ic-chunks of 8. 8 warps = 2(M) x 4(N); warp tile M=32 x N=64.
template<int CIN, bool RELU_IN, bool BIAS>
__global__ __launch_bounds__(256) void conv3x3_tc(
    const float* __restrict__ in, const float* __restrict__ w,
    const float* __restrict__ bias, float* __restrict__ out, int Cout)
{
    __shared__ float xs[8*328];          // [ic8][18x18, pitch 328 (≡8 mod 32)]
    __shared__ float ws[9*64*12];        // [tap][oc64][ic8, pitch 12]

    int b    = blockIdx.x >> 4;
    int tile = blockIdx.x & 15;
    int oy0  = (tile >> 2) << 4;
    int ox0  = (tile & 3) << 4;
    int ocBase = blockIdx.y << 6;

    int tid  = threadIdx.x;
    int lane = tid & 31, warp = tid >> 5;
    int wm = warp >> 2, wn = warp & 3;
    int g = lane >> 2, t = lane & 3;

    float acc[2][8][4];
#pragma unroll
    for (int am = 0; am < 2; am++)
#pragma unroll
        for (int ng = 0; ng < 8; ng++)
#pragma unroll
            for (int j = 0; j < 4; j++) acc[am][ng][j] = 0.f;

    for (int ic0 = 0; ic0 < CIN; ic0 += 8) {
        __syncthreads();
        // stage x chunk: 8 ic x 18x18 (halo, zero-pad, optional relu)
        for (int i = tid; i < 8*324; i += 256) {
            int ic = i / 324, rem = i - ic*324;
            int r = rem / 18, c = rem - r*18;
            int gy = oy0 - 1 + r, gx = ox0 - 1 + c;
            float v = 0.f;
            if ((unsigned)gy < 64u && (unsigned)gx < 64u) {
                v = in[(((size_t)(b*CIN + ic0 + ic))*64 + gy)*64 + gx];
                if (RELU_IN) v = fmaxf(v, 0.f);
            }
            xs[ic*328 + rem] = v;
        }
        // stage w chunk: [tap][oc][ic]
        for (int i = tid; i < 64*72; i += 256) {
            int oc = i / 72, rem = i - oc*72;
            int ic = rem / 9, tap = rem - ic*9;
            ws[tap*768 + oc*12 + ic] =
                w[((size_t)(ocBase + oc)*CIN + ic0)*9 + rem];
        }
        __syncthreads();

#pragma unroll
        for (int kh = 0; kh < 3; kh++) {
#pragma unroll
            for (int kw = 0; kw < 3; kw++) {
                int tap = kh*3 + kw;
                uint32_t a[2][4];
#pragma unroll
                for (int am = 0; am < 2; am++) {
                    const float* wp = ws + tap*768 + (wm*32 + am*16)*12;
                    a[am][0] = __float_as_uint(wp[(g  )*12 + t]);
                    a[am][1] = __float_as_uint(wp[(g+8)*12 + t]);
                    a[am][2] = __float_as_uint(wp[(g  )*12 + t+4]);
                    a[am][3] = __float_as_uint(wp[(g+8)*12 + t+4]);
                }
#pragma unroll
                for (int ng = 0; ng < 8; ng++) {
                    int r  = (wn << 2) + (ng >> 1);
                    int c0 = (ng & 1) << 3;
                    const float* xp = xs + (r+kh)*18 + c0 + kw + g;
                    uint32_t b0 = __float_as_uint(xp[ t   *328]);
                    uint32_t b1 = __float_as_uint(xp[(t+4)*328]);
                    mma_tf32(acc[0][ng], a[0], b0, b1);
                    mma_tf32(acc[1][ng], a[1], b0, b1);
                }
            }
        }
    }

#pragma unroll
    for (int am = 0; am < 2; am++) {
        int oc0 = ocBase + wm*32 + am*16 + g;
        float bv0 = BIAS ? bias[oc0]     : 0.f;
        float bv1 = BIAS ? bias[oc0 + 8] : 0.f;
#pragma unroll
        for (int ng = 0; ng < 8; ng++) {
            int r = (wn << 2) + (ng >> 1);
            int c = ((ng & 1) << 3) + 2*t;
            size_t o0 = ((size_t)(b*Cout + oc0)*64 + oy0 + r)*64 + ox0 + c;
            size_t o1 = o0 + (size_t)8*64*64;
            *(float2*)(out + o0) = make_float2(acc[am][ng][0]+bv0, acc[am][ng][1]+bv0);
            *(float2*)(out + o1) = make_float2(acc[am][ng][2]+bv1, acc[am][ng][3]+bv1);
        }
    }
}

// ---------------- 1x1 conv (relu in) + residual add, tensor-core tf32 ------
// N=256 px tile, M=64 oc, K=128 in chunks of 16.
__global__ __launch_bounds__(256) void conv1x1_res_tc(
    const float* __restrict__ t_, const float* __restrict__ w2,
    float* __restrict__ l)
{
    __shared__ float ts[16*264];   // [k16][px256, pitch 264 (≡8 mod 32)]
    __shared__ float ws[64*20];    // [oc64][k16, pitch 20]

    int b   = blockIdx.x >> 4;
    int px0 = (blockIdx.x & 15) << 8;
    int ocBase = blockIdx.y << 6;
    int tid  = threadIdx.x;
    int lane = tid & 31, warp = tid >> 5;
    int wm = warp >> 2, wn = warp & 3;
    int g = lane >> 2, tt = lane & 3;

    float acc[2][8][4];
#pragma unroll
    for (int am = 0; am < 2; am++)
#pragma unroll
        for (int ng = 0; ng < 8; ng++)
#pragma unroll
            for (int j = 0; j < 4; j++) acc[am][ng][j] = 0.f;

    for (int kc = 0; kc < 128; kc += 16) {
        __syncthreads();
        for (int i = tid; i < 4096; i += 256) {
            int k = i >> 8, p = i & 255;
            ts[k*264 + p] = fmaxf(t_[((size_t)(b*128 + kc + k))*4096 + px0 + p], 0.f);
        }
        for (int i = tid; i < 1024; i += 256) {
            int oc = i >> 4, k = i & 15;
            ws[oc*20 + k] = w2[(size_t)(ocBase + oc)*128 + kc + k];
        }
        __syncthreads();
#pragma unroll
        for (int ks = 0; ks < 2; ks++) {
            int k0 = ks*8;
            uint32_t a[2][4];
#pragma unroll
            for (int am = 0; am < 2; am++) {
                const float* wp = ws + (wm*32 + am*16)*20 + k0;
                a[am][0] = __float_as_uint(wp[(g  )*20 + tt]);
                a[am][1] = __float_as_uint(wp[(g+8)*20 + tt]);
                a[am][2] = __float_as_uint(wp[(g  )*20 + tt+4]);
                a[am][3] = __float_as_uint(wp[(g+8)*20 + tt+4]);
            }
#pragma unroll
            for (int ng = 0; ng < 8; ng++) {
                int n0 = wn*64 + ng*8;
                uint32_t b0 = __float_as_uint(ts[(k0+tt  )*264 + n0 + g]);
                uint32_t b1 = __float_as_uint(ts[(k0+tt+4)*264 + n0 + g]);
                mma_tf32(acc[0][ng], a[0], b0, b1);
                mma_tf32(acc[1][ng], a[1], b0, b1);
            }
        }
    }

#pragma unroll
    for (int am = 0; am < 2; am++) {
        int oc0 = ocBase + wm*32 + am*16 + g;
#pragma unroll
        for (int ng = 0; ng < 8; ng++) {
            int p = px0 + wn*64 + ng*8 + 2*tt;
            size_t o0 = ((size_t)(b*256 + oc0))*4096 + p;
            size_t o1 = o0 + (size_t)8*4096;
            float2 v0 = *(float2*)(l + o0);
            float2 v1 = *(float2*)(l + o1);
            v0.x += acc[am][ng][0]; v0.y += acc[am][ng][1];
            v1.x += acc[am][ng][2]; v1.y += acc[am][ng][3];
            *(float2*)(l + o0) = v0;
            *(float2*)(l + o1) = v1;
        }
    }
}

// ---------------- channel attention: pooled reductions ---------------------
__global__ void pool_kernel() {
    int bc = blockIdx.x;
    const float* p = g_l + (size_t)bc*4096;
    int tid = threadIdx.x;
    float s = 0.f, m = -3.402823466e38f;
    for (int i = tid; i < 4096; i += 256) {
        float v = p[i];
        s += v; m = fmaxf(m, v);
    }
    __shared__ float ss[256], smx[256];
    ss[tid] = s; smx[tid] = m;
    __syncthreads();
    for (int st = 128; st > 0; st >>= 1) {
        if (tid < st) { ss[tid] += ss[tid+st]; smx[tid] = fmaxf(smx[tid], smx[tid+st]); }
        __syncthreads();
    }
    if (tid == 0) { g_avg[bc] = ss[0] * (1.f/4096.f); g_mx[bc] = smx[0]; }
}

// ---------------- channel attention MLP (tiny) -----------------------------
__global__ void camlp_kernel(const float* __restrict__ w1,
                             const float* __restrict__ w2) {
    int b = blockIdx.x;
    int tid = threadIdx.x;
    __shared__ float av[256], mv[256], ha[16], hm[16];
    av[tid] = g_avg[b*256 + tid];
    mv[tid] = g_mx[b*256 + tid];
    __syncthreads();
    if (tid < 16) {
        float sa = 0.f, sm_ = 0.f;
        for (int c = 0; c < 256; c++) {
            float wv = w1[tid*256 + c];
            sa  += av[c]*wv;
            sm_ += mv[c]*wv;
        }
        ha[tid] = fmaxf(sa, 0.f);
        hm[tid] = fmaxf(sm_, 0.f);
    }
    __syncthreads();
    float oa = 0.f, om = 0.f;
#pragma unroll
    for (int j = 0; j < 16; j++) {
        float wv = w2[tid*16 + j];
        oa += ha[j]*wv;
        om += hm[j]*wv;
    }
    g_catt[b*256 + tid] = sigmoidf_(oa + om);
}

// ---------------- spatial stats of channel-scaled l ------------------------
__global__ void spatial_stats_kernel() {
    int b   = blockIdx.x >> 4;
    int px  = ((blockIdx.x & 15) << 8) + threadIdx.x;
    __shared__ float ca[256];
    ca[threadIdx.x] = g_catt[b*256 + threadIdx.x];
    __syncthreads();
    float s = 0.f, m = -3.402823466e38f;
    for (int ch = 0; ch < 256; ch++) {
        float v = g_l[((size_t)(b*256 + ch))*4096 + px] * ca[ch];
        s += v; m = fmaxf(m, v);
    }
    g_s2[((size_t)(b*2 + 0))*4096 + px] = s * (1.f/256.f);
    g_s2[((size_t)(b*2 + 1))*4096 + px] = m;
}

// ---------------- spatial attention conv (2->1, 3x3, pad1) -----------------
__global__ void saconv_kernel(const float* __restrict__ saw) {
    int b  = blockIdx.x >> 4;
    int px = ((blockIdx.x & 15) << 8) + threadIdx.x;
    int py = px >> 6, pxx = px & 63;
    __shared__ float w[18];
    if (threadIdx.x < 18) w[threadIdx.x] = saw[threadIdx.x];
    __syncthreads();
    float a = 0.f;
#pragma unroll
    for (int ch = 0; ch < 2; ch++)
#pragma unroll
        for (int kh = 0; kh < 3; kh++)
#pragma unroll
            for (int kw = 0; kw < 3; kw++) {
                int gy = py - 1 + kh, gx = pxx - 1 + kw;
                if ((unsigned)gy < 64u && (unsigned)gx < 64u)
                    a += g_s2[((size_t)(b*2 + ch))*4096 + gy*64 + gx] * w[ch*9 + kh*3 + kw];
            }
    g_satt[b*4096 + px] = sigmoidf_(a);
}

// ---------------- LISTA persistent tensor-core kernel ----------------------
#define ZS_OFF   0
#define YL_OFF   16640
#define LAM_OFF  33280
#define SS_OFF   49920              // 2 x 2304 (double-buffered [n][9])
#define XSH_OFF  49920              // aliases SS (init phase only)
#define DSH_OFF  16640              // aliases YL+LAM (epilogue only)
#define LISTA_SMEM ((49920 + 2*2304) * 4)

__global__ __launch_bounds__(256, 1) void lista_kernel(
    const float* __restrict__ x, const float* __restrict__ Dict,
    const float* __restrict__ Lp, const int* __restrict__ iterp,
    float* __restrict__ zOut, float* __restrict__ xrOut)
{
    extern __shared__ __align__(16) float smem[];
    float* zs  = smem + ZS_OFF;     // [64][260]
    float* yl  = smem + YL_OFF;     // [64][260]
    float* lam = smem + LAM_OFF;    // [64][260]
    float* sS  = smem + SS_OFF;     // [2][256][9]
    float* xsh = smem + XSH_OFF;    // [64][68]

    int tid = threadIdx.x;
    int gp0 = blockIdx.x * 64;
    int b   = gp0 >> 12;
    int px0 = gp0 & 4095;
    float invL = 1.f / *Lp;
    int iters = *iterp;

    for (int i = tid; i < 4096; i += 256) {
        int c = i >> 6, p = i & 63;
        xsh[p*68 + c] = x[((size_t)(b*64 + c))*4096 + px0 + p];
    }
    for (int i = tid; i < 16384; i += 256) {
        int n = i >> 6, p = i & 63;
        float lv = g_l[((size_t)(b*256 + n))*4096 + px0 + p];
        lam[p*260 + n] = lv * g_catt[b*256 + n] * g_satt[b*4096 + px0 + p] * invL;
    }
    __syncthreads();

    {
        int n0 = tid & 63;
        int pg = tid >> 6;
        float acc[16][4];
#pragma unroll
        for (int p = 0; p < 16; p++)
#pragma unroll
            for (int j = 0; j < 4; j++) acc[p][j] = 0.f;
        for (int c = 0; c < 64; c++) {
            float d0 = Dict[c*256 + n0];
            float d1 = Dict[c*256 + n0 + 64];
            float d2 = Dict[c*256 + n0 + 128];
            float d3 = Dict[c*256 + n0 + 192];
#pragma unroll
            for (int p = 0; p < 16; p++) {
                float xv = xsh[(pg*16 + p)*68 + c];
                acc[p][0] += xv*d0;
                acc[p][1] += xv*d1;
                acc[p][2] += xv*d2;
                acc[p][3] += xv*d3;
            }
        }
#pragma unroll
        for (int p = 0; p < 16; p++)
#pragma unroll
            for (int j = 0; j < 4; j++) {
                int idx = (pg*16 + p)*260 + n0 + 64*j;
                yl[idx] = acc[p][j]*invL;
                zs[idx] = softt(acc[p][j], lam[idx]);
            }
    }

    const int lane = tid & 31;
    const int warp = tid >> 5;
    const int wm   = warp >> 2;
    const int wn   = warp & 3;
    const int g    = lane >> 2;
    const int t    = lane & 3;
    const int mBase = wm*32;
    const int nBase = wn*64;

    float rS[8];
#pragma unroll
    for (int k = 0; k < 8; k++) rS[k] = g_S[k*256 + tid];

    for (int it = 0; it < iters; it++) {
        float acc[2][8][4];
#pragma unroll
        for (int am = 0; am < 2; am++)
#pragma unroll
            for (int nt = 0; nt < 8; nt++)
#pragma unroll
                for (int j = 0; j < 4; j++) acc[am][nt][j] = 0.f;

#pragma unroll
        for (int k = 0; k < 8; k++) sS[tid*9 + k] = rS[k];

        for (int kc = 0; kc < 32; kc++) {
            if (kc + 1 < 32) {
#pragma unroll
                for (int k = 0; k < 8; k++)
                    rS[k] = g_S[((kc+1)*8 + k)*256 + tid];
            }
            __syncthreads();

            int k0 = kc*8;
            uint32_t a[2][4];
#pragma unroll
            for (int am = 0; am < 2; am++) {
                int row = mBase + am*16 + g;
                a[am][0] = f2tf32(zs[row*260 + k0 + t]);
                a[am][1] = f2tf32(zs[(row+8)*260 + k0 + t]);
                a[am][2] = f2tf32(zs[row*260 + k0 + t + 4]);
                a[am][3] = f2tf32(zs[(row+8)*260 + k0 + t + 4]);
            }
            const float* sb = sS + (kc & 1)*2304;
#pragma unroll
            for (int nt = 0; nt < 8; nt++) {
                int nn = nBase + nt*8 + g;
                uint32_t b0 = __float_as_uint(sb[nn*9 + t]);
                uint32_t b1 = __float_as_uint(sb[nn*9 + t + 4]);
                mma_tf32(acc[0][nt], a[0], b0, b1);
                mma_tf32(acc[1][nt], a[1], b0, b1);
            }
            if (kc + 1 < 32) {
#pragma unroll
                for (int k = 0; k < 8; k++)
                    sS[((kc+1)&1)*2304 + tid*9 + k] = rS[k];
            }
        }

        if (it + 1 < iters) {
#pragma unroll
            for (int k = 0; k < 8; k++) rS[k] = g_S[k*256 + tid];
        }
        __syncthreads();

#pragma unroll
        for (int am = 0; am < 2; am++) {
#pragma unroll
            for (int nt = 0; nt < 8; nt++) {
                int row = mBase + am*16 + g;
                int col = nBase + nt*8 + 2*t;
                int i0 = row*260 + col;
                int i1 = (row+8)*260 + col;
                zs[i0]   = softt(acc[am][nt][0] + yl[i0],   lam[i0]);
                zs[i0+1] = softt(acc[am][nt][1] + yl[i0+1], lam[i0+1]);
                zs[i1]   = softt(acc[am][nt][2] + yl[i1],   lam[i1]);
                zs[i1+1] = softt(acc[am][nt][3] + yl[i1+1], lam[i1+1]);
            }
        }
        __syncthreads();
    }

    for (int i = tid; i < 16384; i += 256) {
        int n = i >> 6, p = i & 63;
        zOut[((size_t)(b*256 + n))*4096 + px0 + p] = zs[p*260 + n];
    }
    __syncthreads();

    float* dsh = smem + DSH_OFF;
    for (int i = tid; i < 16384; i += 256) {
        int c = i >> 8, a = i & 255;
        dsh[a*68 + c] = Dict[c*256 + a];
    }
    __syncthreads();

    {
        int p = tid & 63, cg = tid >> 6;
        float acc[16];
#pragma unroll
        for (int j = 0; j < 16; j++) acc[j] = 0.f;
        for (int a = 0; a < 256; a++) {
            float zv = zs[p*260 + a];
            const float4* dr = (const float4*)&dsh[a*68 + cg*16];
            float4 d0 = dr[0], d1 = dr[1], d2 = dr[2], d3 = dr[3];
            acc[0]  += zv*d0.x; acc[1]  += zv*d0.y; acc[2]  += zv*d0.z; acc[3]  += zv*d0.w;
            acc[4]  += zv*d1.x; acc[5]  += zv*d1.y; acc[6]  += zv*d1.z; acc[7]  += zv*d1.w;
            acc[8]  += zv*d2.x; acc[9]  += zv*d2.y; acc[10] += zv*d2.z; acc[11] += zv*d2.w;
            acc[12] += zv*d3.x; acc[13] += zv*d3.y; acc[14] += zv*d3.z; acc[15] += zv*d3.w;
        }
#pragma unroll
        for (int j = 0; j < 16; j++)
            xrOut[((size_t)(b*64 + cg*16 + j))*4096 + px0 + p] = acc[j];
    }
}

// ---------------- launch ----------------------------------------------------
extern "C" void kernel_launch(void* const* d_in, const int* in_sizes, int n_in,
                              void* d_out, int out_size)
{
    const float* x      = (const float*)d_in[0];
    const float* conv_w = (const float*)d_in[1];
    const float* conv_b = (const float*)d_in[2];
    const float* r1w1   = (const float*)d_in[3];
    const float* r1w2   = (const float*)d_in[4];
    const float* r2w1   = (const float*)d_in[5];
    const float* r2w2   = (const float*)d_in[6];
    const float* caw1   = (const float*)d_in[7];
    const float* caw2   = (const float*)d_in[8];
    const float* saw    = (const float*)d_in[9];
    const float* Dict   = (const float*)d_in[10];
    const float* Lp     = (const float*)d_in[11];
    const int*   itp    = (const int*)d_in[12];

    float* out   = (float*)d_out;
    float* zOut  = out;
    float* xrOut = out + (size_t)8*256*4096;
    float* dOut  = xrOut + (size_t)8*64*4096;

    float *lp, *tp;
    cudaGetSymbolAddress((void**)&lp, g_l);
    cudaGetSymbolAddress((void**)&tp, g_t);

    compute_S_kernel<<<256, 256>>>(Dict, Lp);

    conv3x3_tc<64, false, true><<<dim3(128, 4), 256>>>(x, conv_w, conv_b, lp, 256);

    conv3x3_tc<256, true, false><<<dim3(128, 2), 256>>>(lp, r1w1, nullptr, tp, 128);
    conv1x1_res_tc<<<dim3(128, 4), 256>>>(tp, r1w2, lp);

    conv3x3_tc<256, true, false><<<dim3(128, 2), 256>>>(lp, r2w1, nullptr, tp, 128);
    conv1x1_res_tc<<<dim3(128, 4), 256>>>(tp, r2w2, lp);

    pool_kernel<<<2048, 256>>>();
    camlp_kernel<<<8, 256>>>(caw1, caw2);
    spatial_stats_kernel<<<128, 256>>>();
    saconv_kernel<<<128, 256>>>(saw);

    cudaFuncSetAttribute(lista_kernel, cudaFuncAttributeMaxDynamicSharedMemorySize, LISTA_SMEM);
    lista_kernel<<<512, 256, LISTA_SMEM>>>(x, Dict, Lp, itp, zOut, xrOut);

    cudaMemcpyAsync(dOut, Dict, (size_t)64*256*sizeof(float), cudaMemcpyDeviceToDevice);
}

// round 8
// speedup vs baseline: 2.3908x; 1.2210x over previous
#include <cuda_runtime.h>
#include <math.h>
#include <stdint.h>

// ---------------- scratch (device globals; no allocation allowed) ----------
__device__ float g_l[8*256*64*64];     // encoder feature map l
__device__ float g_t[8*128*64*64];     // res-block intermediate (relu'd)
__device__ float g_S[256*256];         // LISTA matrix I - G/L (tf32-rounded)
__device__ float g_avg[8*256];
__device__ float g_mx[8*256];
__device__ float g_catt[8*256];        // channel attention (sigmoid)
__device__ float g_s2[8*2*64*64];      // spatial-attention input
__device__ float g_satt[8*64*64];      // spatial attention (sigmoid)

static __device__ __forceinline__ float softt(float v, float la) {
    float a = fabsf(v) - la;
    a = a > 0.f ? a : 0.f;
    return copysignf(a, v);
}
static __device__ __forceinline__ float sigmoidf_(float v) {
    return 1.f / (1.f + expf(-v));
}
static __device__ __forceinline__ uint32_t f2tf32(float f) {
    uint32_t r;
    asm("cvt.rna.tf32.f32 %0, %1;" : "=r"(r) : "f"(f));
    return r;
}
static __device__ __forceinline__ void mma_tf32(float* c, const uint32_t* a,
                                                uint32_t b0, uint32_t b1) {
    asm volatile(
        "mma.sync.aligned.m16n8k8.row.col.f32.tf32.tf32.f32 "
        "{%0,%1,%2,%3}, {%4,%5,%6,%7}, {%8,%9}, {%0,%1,%2,%3};\n"
        : "+f"(c[0]), "+f"(c[1]), "+f"(c[2]), "+f"(c[3])
        : "r"(a[0]), "r"(a[1]), "r"(a[2]), "r"(a[3]), "r"(b0), "r"(b1));
}
static __device__ __forceinline__ uint32_t smem_u32(const void* p) {
    return (uint32_t)__cvta_generic_to_shared(p);
}
static __device__ __forceinline__ void cp4(uint32_t dst, const void* src, bool pred) {
    int sz = pred ? 4 : 0;
    asm volatile("cp.async.ca.shared.global [%0], [%1], 4, %2;\n"
                 :: "r"(dst), "l"(src), "r"(sz));
}
static __device__ __forceinline__ void cp16(uint32_t dst, const void* src) {
    asm volatile("cp.async.cg.shared.global [%0], [%1], 16;\n"
                 :: "r"(dst), "l"(src));
}
static __device__ __forceinline__ void cp_commit() {
    asm volatile("cp.async.commit_group;\n");
}
template<int N> static __device__ __forceinline__ void cp_wait() {
    asm volatile("cp.async.wait_group %0;\n" :: "n"(N));
}

// ---------------- S = I - (Dict^T Dict)/L  (symmetric, tf32-rounded) -------
__global__ void compute_S_kernel(const float* __restrict__ Dict,
                                 const float* __restrict__ Lp) {
    int i = blockIdx.x, j = threadIdx.x;
    float L = *Lp;
    float g = 0.f;
#pragma unroll 8
    for (int c = 0; c < 64; c++) g += Dict[c*256 + i] * Dict[c*256 + j];
    float v = (i == j ? 1.f : 0.f) - g / L;
    g_S[i*256 + j] = __uint_as_float(f2tf32(v));
}

// ---------------- 3x3 conv, pad 1, NCHW, tensor-core tf32, cp.async --------
// 16x16 spatial tile (N=256 px), 64 oc (M). 8 warps = 2(M) x 4(N).
// Double-buffered ic-chunks of 8 staged with cp.async overlapped with MMA.
#define C3_XS  2624                   // 8*328 floats per buffer
#define C3_WS  6912                   // 9*64*12 floats per buffer
#define CONV3_SMEM ((2*C3_XS + 2*C3_WS)*4)

template<int CIN, bool RELU_IN, bool RELU_OUT, bool BIAS>
__global__ __launch_bounds__(256, 2) void conv3x3_tc(
    const float* __restrict__ in, const float* __restrict__ w,
    const float* __restrict__ bias, float* __restrict__ out, int Cout)
{
    extern __shared__ __align__(16) float sm[];
    float* xsb = sm;                  // [2][8][18x18 pitch 328]
    float* wsb = sm + 2*C3_XS;        // [2][tap][oc64][ic8 pitch 12]

    int b    = blockIdx.x >> 4;
    int tile = blockIdx.x & 15;
    int oy0  = (tile >> 2) << 4;
    int ox0  = (tile & 3) << 4;
    int ocBase = blockIdx.y << 6;

    int tid  = threadIdx.x;
    int lane = tid & 31, warp = tid >> 5;
    int wm = warp >> 2, wn = warp & 3;
    int g = lane >> 2, t = lane & 3;

    const int NCH = CIN / 8;

    float acc[2][8][4];
#pragma unroll
    for (int am = 0; am < 2; am++)
#pragma unroll
        for (int ng = 0; ng < 8; ng++)
#pragma unroll
            for (int j = 0; j < 4; j++) acc[am][ng][j] = 0.f;

    // stage chunk `ch` into buffer `bi`
    auto stage = [&](int ch, int bi) {
        int ic0 = ch << 3;
        float* xs = xsb + bi*C3_XS;
        float* ws = wsb + bi*C3_WS;
        for (int i = tid; i < 8*324; i += 256) {
            int ic = i / 324, rem = i - ic*324;
            int r = rem / 18, c = rem - r*18;
            int gy = oy0 - 1 + r, gx = ox0 - 1 + c;
            bool ok = ((unsigned)gy < 64u) && ((unsigned)gx < 64u);
            const float* src = ok
                ? in + (((size_t)(b*CIN + ic0 + ic))*64 + gy)*64 + gx
                : in;
            cp4(smem_u32(xs + ic*328 + rem), src, ok);
        }
        for (int i = tid; i < 64*72; i += 256) {
            int oc = i / 72, rem = i - oc*72;
            int ic = rem / 9, tap = rem - ic*9;
            cp4(smem_u32(ws + tap*768 + oc*12 + ic),
                w + ((size_t)(ocBase + oc)*CIN + ic0)*9 + rem, true);
        }
        cp_commit();
    };

    stage(0, 0);
    for (int ch = 0; ch < NCH; ch++) {
        if (ch + 1 < NCH) { stage(ch + 1, (ch + 1) & 1); cp_wait<1>(); }
        else              { cp_wait<0>(); }
        __syncthreads();

        const float* xs = xsb + (ch & 1)*C3_XS;
        const float* ws = wsb + (ch & 1)*C3_WS;
#pragma unroll
        for (int kh = 0; kh < 3; kh++) {
#pragma unroll
            for (int kw = 0; kw < 3; kw++) {
                int tap = kh*3 + kw;
                uint32_t a[2][4];
#pragma unroll
                for (int am = 0; am < 2; am++) {
                    const float* wp = ws + tap*768 + (wm*32 + am*16)*12;
                    a[am][0] = __float_as_uint(wp[(g  )*12 + t]);
                    a[am][1] = __float_as_uint(wp[(g+8)*12 + t]);
                    a[am][2] = __float_as_uint(wp[(g  )*12 + t+4]);
                    a[am][3] = __float_as_uint(wp[(g+8)*12 + t+4]);
                }
#pragma unroll
                for (int ng = 0; ng < 8; ng++) {
                    int r  = (wn << 2) + (ng >> 1);
                    int c0 = (ng & 1) << 3;
                    const float* xp = xs + (r+kh)*18 + c0 + kw + g;
                    float v0 = xp[ t   *328];
                    float v1 = xp[(t+4)*328];
                    if (RELU_IN) { v0 = fmaxf(v0, 0.f); v1 = fmaxf(v1, 0.f); }
                    uint32_t b0 = __float_as_uint(v0);
                    uint32_t b1 = __float_as_uint(v1);
                    mma_tf32(acc[0][ng], a[0], b0, b1);
                    mma_tf32(acc[1][ng], a[1], b0, b1);
                }
            }
        }
        __syncthreads();
    }

#pragma unroll
    for (int am = 0; am < 2; am++) {
        int oc0 = ocBase + wm*32 + am*16 + g;
        float bv0 = BIAS ? bias[oc0]     : 0.f;
        float bv1 = BIAS ? bias[oc0 + 8] : 0.f;
#pragma unroll
        for (int ng = 0; ng < 8; ng++) {
            int r = (wn << 2) + (ng >> 1);
            int c = ((ng & 1) << 3) + 2*t;
            size_t o0 = ((size_t)(b*Cout + oc0)*64 + oy0 + r)*64 + ox0 + c;
            size_t o1 = o0 + (size_t)8*64*64;
            float r00 = acc[am][ng][0]+bv0, r01 = acc[am][ng][1]+bv0;
            float r10 = acc[am][ng][2]+bv1, r11 = acc[am][ng][3]+bv1;
            if (RELU_OUT) {
                r00 = fmaxf(r00, 0.f); r01 = fmaxf(r01, 0.f);
                r10 = fmaxf(r10, 0.f); r11 = fmaxf(r11, 0.f);
            }
            *(float2*)(out + o0) = make_float2(r00, r01);
            *(float2*)(out + o1) = make_float2(r10, r11);
        }
    }
}

// ---------------- 1x1 conv + residual add, tensor-core tf32, cp.async ------
// Input t is already relu'd by the producer. N=256 px, M=64 oc, K chunks 16.
__global__ __launch_bounds__(256) void conv1x1_res_tc(
    const float* __restrict__ t_, const float* __restrict__ w2,
    float* __restrict__ l)
{
    __shared__ __align__(16) float ts[2][16*264];  // [k16][px256 pitch 264]
    __shared__ __align__(16) float ws[2][64*20];   // [oc64][k16 pitch 20]

    int b   = blockIdx.x >> 4;
    int px0 = (blockIdx.x & 15) << 8;
    int ocBase = blockIdx.y << 6;
    int tid  = threadIdx.x;
    int lane = tid & 31, warp = tid >> 5;
    int wm = warp >> 2, wn = warp & 3;
    int g = lane >> 2, tt = lane & 3;

    float acc[2][8][4];
#pragma unroll
    for (int am = 0; am < 2; am++)
#pragma unroll
        for (int ng = 0; ng < 8; ng++)
#pragma unroll
            for (int j = 0; j < 4; j++) acc[am][ng][j] = 0.f;

    auto stage = [&](int ch, int bi) {
        int kc = ch << 4;
        for (int i = tid; i < 1024; i += 256) {
            int k = i >> 6, p4 = (i & 63) << 2;
            cp16(smem_u32(&ts[bi][k*264 + p4]),
                 t_ + ((size_t)(b*128 + kc + k))*4096 + px0 + p4);
        }
        {
            int i = tid;  // 256 = 64 oc x 4 quads
            int oc = i >> 2, kq = (i & 3) << 2;
            cp16(smem_u32(&ws[bi][oc*20 + kq]),
                 w2 + (size_t)(ocBase + oc)*128 + kc + kq);
        }
        cp_commit();
    };

    stage(0, 0);
    for (int ch = 0; ch < 8; ch++) {
        if (ch + 1 < 8) { stage(ch + 1, (ch + 1) & 1); cp_wait<1>(); }
        else            { cp_wait<0>(); }
        __syncthreads();

        const float* tsb = ts[ch & 1];
        const float* wsb = ws[ch & 1];
#pragma unroll
        for (int ks = 0; ks < 2; ks++) {
            int k0 = ks*8;
            uint32_t a[2][4];
#pragma unroll
            for (int am = 0; am < 2; am++) {
                const float* wp = wsb + (wm*32 + am*16)*20 + k0;
                a[am][0] = __float_as_uint(wp[(g  )*20 + tt]);
                a[am][1] = __float_as_uint(wp[(g+8)*20 + tt]);
                a[am][2] = __float_as_uint(wp[(g  )*20 + tt+4]);
                a[am][3] = __float_as_uint(wp[(g+8)*20 + tt+4]);
            }
#pragma unroll
            for (int ng = 0; ng < 8; ng++) {
                int n0 = wn*64 + ng*8;
                uint32_t b0 = __float_as_uint(tsb[(k0+tt  )*264 + n0 + g]);
                uint32_t b1 = __float_as_uint(tsb[(k0+tt+4)*264 + n0 + g]);
                mma_tf32(acc[0][ng], a[0], b0, b1);
                mma_tf32(acc[1][ng], a[1], b0, b1);
            }
        }
        __syncthreads();
    }

#pragma unroll
    for (int am = 0; am < 2; am++) {
        int oc0 = ocBase + wm*32 + am*16 + g;
#pragma unroll
        for (int ng = 0; ng < 8; ng++) {
            int p = px0 + wn*64 + ng*8 + 2*tt;
            size_t o0 = ((size_t)(b*256 + oc0))*4096 + p;
            size_t o1 = o0 + (size_t)8*4096;
            float2 v0 = *(float2*)(l + o0);
            float2 v1 = *(float2*)(l + o1);
            v0.x += acc[am][ng][0]; v0.y += acc[am][ng][1];
            v1.x += acc[am][ng][2]; v1.y += acc[am][ng][3];
            *(float2*)(l + o0) = v0;
            *(float2*)(l + o1) = v1;
        }
    }
}

// ---------------- channel attention: pooled reductions ---------------------
__global__ void pool_kernel() {
    int bc = blockIdx.x;
    const float* p = g_l + (size_t)bc*4096;
    int tid = threadIdx.x;
    float s = 0.f, m = -3.402823466e38f;
    for (int i = tid; i < 4096; i += 256) {
        float v = p[i];
        s += v; m = fmaxf(m, v);
    }
    __shared__ float ss[256], smx[256];
    ss[tid] = s; smx[tid] = m;
    __syncthreads();
    for (int st = 128; st > 0; st >>= 1) {
        if (tid < st) { ss[tid] += ss[tid+st]; smx[tid] = fmaxf(smx[tid], smx[tid+st]); }
        __syncthreads();
    }
    if (tid == 0) { g_avg[bc] = ss[0] * (1.f/4096.f); g_mx[bc] = smx[0]; }
}

// ---------------- channel attention MLP (tiny) -----------------------------
__global__ void camlp_kernel(const float* __restrict__ w1,
                             const float* __restrict__ w2) {
    int b = blockIdx.x;
    int tid = threadIdx.x;
    __shared__ float av[256], mv[256], ha[16], hm[16];
    av[tid] = g_avg[b*256 + tid];
    mv[tid] = g_mx[b*256 + tid];
    __syncthreads();
    if (tid < 16) {
        float sa = 0.f, sm_ = 0.f;
        for (int c = 0; c < 256; c++) {
            float wv = w1[tid*256 + c];
            sa  += av[c]*wv;
            sm_ += mv[c]*wv;
        }
        ha[tid] = fmaxf(sa, 0.f);
        hm[tid] = fmaxf(sm_, 0.f);
    }
    __syncthreads();
    float oa = 0.f, om = 0.f;
#pragma unroll
    for (int j = 0; j < 16; j++) {
        float wv = w2[tid*16 + j];
        oa += ha[j]*wv;
        om += hm[j]*wv;
    }
    g_catt[b*256 + tid] = sigmoidf_(oa + om);
}

// ---------------- spatial stats of channel-scaled l ------------------------
__global__ void spatial_stats_kernel() {
    int b   = blockIdx.x >> 4;
    int px  = ((blockIdx.x & 15) << 8) + threadIdx.x;
    __shared__ float ca[256];
    ca[threadIdx.x] = g_catt[b*256 + threadIdx.x];
    __syncthreads();
    float s = 0.f, m = -3.402823466e38f;
    for (int ch = 0; ch < 256; ch++) {
        float v = g_l[((size_t)(b*256 + ch))*4096 + px] * ca[ch];
        s += v; m = fmaxf(m, v);
    }
    g_s2[((size_t)(b*2 + 0))*4096 + px] = s * (1.f/256.f);
    g_s2[((size_t)(b*2 + 1))*4096 + px] = m;
}

// ---------------- spatial attention conv (2->1, 3x3, pad1) -----------------
__global__ void saconv_kernel(const float* __restrict__ saw) {
    int b  = blockIdx.x >> 4;
    int px = ((blockIdx.x & 15) << 8) + threadIdx.x;
    int py = px >> 6, pxx = px & 63;
    __shared__ float w[18];
    if (threadIdx.x < 18) w[threadIdx.x] = saw[threadIdx.x];
    __syncthreads();
    float a = 0.f;
#pragma unroll
    for (int ch = 0; ch < 2; ch++)
#pragma unroll
        for (int kh = 0; kh < 3; kh++)
#pragma unroll
            for (int kw = 0; kw < 3; kw++) {
                int gy = py - 1 + kh, gx = pxx - 1 + kw;
                if ((unsigned)gy < 64u && (unsigned)gx < 64u)
                    a += g_s2[((size_t)(b*2 + ch))*4096 + gy*64 + gx] * w[ch*9 + kh*3 + kw];
            }
    g_satt[b*4096 + px] = sigmoidf_(a);
}

// ---------------- LISTA persistent tensor-core kernel ----------------------
#define ZS_OFF   0
#define YL_OFF   16640
#define LAM_OFF  33280
#define SS_OFF   49920              // 2 x 2304 (double-buffered [n][9])
#define XSH_OFF  49920              // aliases SS (init phase only)
#define DSH_OFF  16640              // aliases YL+LAM (epilogue only)
#define LISTA_SMEM ((49920 + 2*2304) * 4)

__global__ __launch_bounds__(256, 1) void lista_kernel(
    const float* __restrict__ x, const float* __restrict__ Dict,
    const float* __restrict__ Lp, const int* __restrict__ iterp,
    float* __restrict__ zOut, float* __restrict__ xrOut)
{
    extern __shared__ __align__(16) float smem[];
    float* zs  = smem + ZS_OFF;     // [64][260]
    float* yl  = smem + YL_OFF;     // [64][260]
    float* lam = smem + LAM_OFF;    // [64][260]
    float* sS  = smem + SS_OFF;     // [2][256][9]
    float* xsh = smem + XSH_OFF;    // [64][68]

    int tid = threadIdx.x;
    int gp0 = blockIdx.x * 64;
    int b   = gp0 >> 12;
    int px0 = gp0 & 4095;
    float invL = 1.f / *Lp;
    int iters = *iterp;

    for (int i = tid; i < 4096; i += 256) {
        int c = i >> 6, p = i & 63;
        xsh[p*68 + c] = x[((size_t)(b*64 + c))*4096 + px0 + p];
    }
    for (int i = tid; i < 16384; i += 256) {
        int n = i >> 6, p = i & 63;
        float lv = g_l[((size_t)(b*256 + n))*4096 + px0 + p];
        lam[p*260 + n] = lv * g_catt[b*256 + n] * g_satt[b*4096 + px0 + p] * invL;
    }
    __syncthreads();

    {
        int n0 = tid & 63;
        int pg = tid >> 6;
        float acc[16][4];
#pragma unroll
        for (int p = 0; p < 16; p++)
#pragma unroll
            for (int j = 0; j < 4; j++) acc[p][j] = 0.f;
        for (int c = 0; c < 64; c++) {
            float d0 = Dict[c*256 + n0];
            float d1 = Dict[c*256 + n0 + 64];
            float d2 = Dict[c*256 + n0 + 128];
            float d3 = Dict[c*256 + n0 + 192];
#pragma unroll
            for (int p = 0; p < 16; p++) {
                float xv = xsh[(pg*16 + p)*68 + c];
                acc[p][0] += xv*d0;
                acc[p][1] += xv*d1;
                acc[p][2] += xv*d2;
                acc[p][3] += xv*d3;
            }
        }
#pragma unroll
        for (int p = 0; p < 16; p++)
#pragma unroll
            for (int j = 0; j < 4; j++) {
                int idx = (pg*16 + p)*260 + n0 + 64*j;
                yl[idx] = acc[p][j]*invL;
                zs[idx] = softt(acc[p][j], lam[idx]);
            }
    }

    const int lane = tid & 31;
    const int warp = tid >> 5;
    const int wm   = warp >> 2;
    const int wn   = warp & 3;
    const int g    = lane >> 2;
    const int t    = lane & 3;
    const int mBase = wm*32;
    const int nBase = wn*64;

    float rS[8];
#pragma unroll
    for (int k = 0; k < 8; k++) rS[k] = g_S[k*256 + tid];

    for (int it = 0; it < iters; it++) {
        float acc[2][8][4];
#pragma unroll
        for (int am = 0; am < 2; am++)
#pragma unroll
            for (int nt = 0; nt < 8; nt++)
#pragma unroll
                for (int j = 0; j < 4; j++) acc[am][nt][j] = 0.f;

#pragma unroll
        for (int k = 0; k < 8; k++) sS[tid*9 + k] = rS[k];

        for (int kc = 0; kc < 32; kc++) {
            if (kc + 1 < 32) {
#pragma unroll
                for (int k = 0; k < 8; k++)
                    rS[k] = g_S[((kc+1)*8 + k)*256 + tid];
            }
            __syncthreads();

            int k0 = kc*8;
            uint32_t a[2][4];
#pragma unroll
            for (int am = 0; am < 2; am++) {
                int row = mBase + am*16 + g;
                a[am][0] = f2tf32(zs[row*260 + k0 + t]);
                a[am][1] = f2tf32(zs[(row+8)*260 + k0 + t]);
                a[am][2] = f2tf32(zs[row*260 + k0 + t + 4]);
                a[am][3] = f2tf32(zs[(row+8)*260 + k0 + t + 4]);
            }
            const float* sb = sS + (kc & 1)*2304;
#pragma unroll
            for (int nt = 0; nt < 8; nt++) {
                int nn = nBase + nt*8 + g;
                uint32_t b0 = __float_as_uint(sb[nn*9 + t]);
                uint32_t b1 = __float_as_uint(sb[nn*9 + t + 4]);
                mma_tf32(acc[0][nt], a[0], b0, b1);
                mma_tf32(acc[1][nt], a[1], b0, b1);
            }
            if (kc + 1 < 32) {
#pragma unroll
                for (int k = 0; k < 8; k++)
                    sS[((kc+1)&1)*2304 + tid*9 + k] = rS[k];
            }
        }

        if (it + 1 < iters) {
#pragma unroll
            for (int k = 0; k < 8; k++) rS[k] = g_S[k*256 + tid];
        }
        __syncthreads();

#pragma unroll
        for (int am = 0; am < 2; am++) {
#pragma unroll
            for (int nt = 0; nt < 8; nt++) {
                int row = mBase + am*16 + g;
                int col = nBase + nt*8 + 2*t;
                int i0 = row*260 + col;
                int i1 = (row+8)*260 + col;
                zs[i0]   = softt(acc[am][nt][0] + yl[i0],   lam[i0]);
                zs[i0+1] = softt(acc[am][nt][1] + yl[i0+1], lam[i0+1]);
                zs[i1]   = softt(acc[am][nt][2] + yl[i1],   lam[i1]);
                zs[i1+1] = softt(acc[am][nt][3] + yl[i1+1], lam[i1+1]);
            }
        }
        __syncthreads();
    }

    for (int i = tid; i < 16384; i += 256) {
        int n = i >> 6, p = i & 63;
        zOut[((size_t)(b*256 + n))*4096 + px0 + p] = zs[p*260 + n];
    }
    __syncthreads();

    float* dsh = smem + DSH_OFF;
    for (int i = tid; i < 16384; i += 256) {
        int c = i >> 8, a = i & 255;
        dsh[a*68 + c] = Dict[c*256 + a];
    }
    __syncthreads();

    {
        int p = tid & 63, cg = tid >> 6;
        float acc[16];
#pragma unroll
        for (int j = 0; j < 16; j++) acc[j] = 0.f;
        for (int a = 0; a < 256; a++) {
            float zv = zs[p*260 + a];
            const float4* dr = (const float4*)&dsh[a*68 + cg*16];
            float4 d0 = dr[0], d1 = dr[1], d2 = dr[2], d3 = dr[3];
            acc[0]  += zv*d0.x; acc[1]  += zv*d0.y; acc[2]  += zv*d0.z; acc[3]  += zv*d0.w;
            acc[4]  += zv*d1.x; acc[5]  += zv*d1.y; acc[6]  += zv*d1.z; acc[7]  += zv*d1.w;
            acc[8]  += zv*d2.x; acc[9]  += zv*d2.y; acc[10] += zv*d2.z; acc[11] += zv*d2.w;
            acc[12] += zv*d3.x; acc[13] += zv*d3.y; acc[14] += zv*d3.z; acc[15] += zv*d3.w;
        }
#pragma unroll
        for (int j = 0; j < 16; j++)
            xrOut[((size_t)(b*64 + cg*16 + j))*4096 + px0 + p] = acc[j];
    }
}

// ---------------- launch ----------------------------------------------------
extern "C" void kernel_launch(void* const* d_in, const int* in_sizes, int n_in,
                              void* d_out, int out_size)
{
    const float* x      = (const float*)d_in[0];
    const float* conv_w = (const float*)d_in[1];
    const float* conv_b = (const float*)d_in[2];
    const float* r1w1   = (const float*)d_in[3];
    const float* r1w2   = (const float*)d_in[4];
    const float* r2w1   = (const float*)d_in[5];
    const float* r2w2   = (const float*)d_in[6];
    const float* caw1   = (const float*)d_in[7];
    const float* caw2   = (const float*)d_in[8];
    const float* saw    = (const float*)d_in[9];
    const float* Dict   = (const float*)d_in[10];
    const float* Lp     = (const float*)d_in[11];
    const int*   itp    = (const int*)d_in[12];

    float* out   = (float*)d_out;
    float* zOut  = out;
    float* xrOut = out + (size_t)8*256*4096;
    float* dOut  = xrOut + (size_t)8*64*4096;

    float *lp, *tp;
    cudaGetSymbolAddress((void**)&lp, g_l);
    cudaGetSymbolAddress((void**)&tp, g_t);

    cudaFuncSetAttribute((const void*)conv3x3_tc<64, false, false, true>,
                         cudaFuncAttributeMaxDynamicSharedMemorySize, CONV3_SMEM);
    cudaFuncSetAttribute((const void*)conv3x3_tc<256, true, true, false>,
                         cudaFuncAttributeMaxDynamicSharedMemorySize, CONV3_SMEM);
    cudaFuncSetAttribute((const void*)lista_kernel,
                         cudaFuncAttributeMaxDynamicSharedMemorySize, LISTA_SMEM);

    compute_S_kernel<<<256, 256>>>(Dict, Lp);

    conv3x3_tc<64, false, false, true><<<dim3(128, 4), 256, CONV3_SMEM>>>(
        x, conv_w, conv_b, lp, 256);

    conv3x3_tc<256, true, true, false><<<dim3(128, 2), 256, CONV3_SMEM>>>(
        lp, r1w1, nullptr, tp, 128);
    conv1x1_res_tc<<<dim3(128, 4), 256>>>(tp, r1w2, lp);

    conv3x3_tc<256, true, true, false><<<dim3(128, 2), 256, CONV3_SMEM>>>(
        lp, r2w1, nullptr, tp, 128);
    conv1x1_res_tc<<<dim3(128, 4), 256>>>(tp, r2w2, lp);

    pool_kernel<<<2048, 256>>>();
    camlp_kernel<<<8, 256>>>(caw1, caw2);
    spatial_stats_kernel<<<128, 256>>>();
    saconv_kernel<<<128, 256>>>(saw);

    lista_kernel<<<512, 256, LISTA_SMEM>>>(x, Dict, Lp, itp, zOut, xrOut);

    cudaMemcpyAsync(dOut, Dict, (size_t)64*256*sizeof(float), cudaMemcpyDeviceToDevice);
}

// round 13
// speedup vs baseline: 3.0595x; 1.2797x over previous
#include <cuda_runtime.h>
#include <math.h>
#include <stdint.h>

// ---------------- scratch (device globals; no allocation allowed) ----------
__device__ float g_l[8*256*64*64];     // encoder feature map l
__device__ float g_t[8*128*64*64];     // res-block intermediate (relu'd)
__device__ float g_Sp[256*256];        // LISTA matrix, mma-fragment-packed
__device__ float g_avg[8*256];
__device__ float g_mx[8*256];
__device__ float g_catt[8*256];        // channel attention (sigmoid)
__device__ float g_s2[8*2*64*64];      // spatial-attention input
__device__ float g_satt[8*64*64];      // spatial attention (sigmoid)

static __device__ __forceinline__ float softt(float v, float la) {
    float a = fabsf(v) - la;
    a = a > 0.f ? a : 0.f;
    return copysignf(a, v);
}
static __device__ __forceinline__ float sigmoidf_(float v) {
    return 1.f / (1.f + expf(-v));
}
static __device__ __forceinline__ uint32_t f2tf32(float f) {
    uint32_t r;
    asm("cvt.rna.tf32.f32 %0, %1;" : "=r"(r) : "f"(f));
    return r;
}
static __device__ __forceinline__ void mma_tf32(float* c, const uint32_t* a,
                                                uint32_t b0, uint32_t b1) {
    asm volatile(
        "mma.sync.aligned.m16n8k8.row.col.f32.tf32.tf32.f32 "
        "{%0,%1,%2,%3}, {%4,%5,%6,%7}, {%8,%9}, {%0,%1,%2,%3};\n"
        : "+f"(c[0]), "+f"(c[1]), "+f"(c[2]), "+f"(c[3])
        : "r"(a[0]), "r"(a[1]), "r"(a[2]), "r"(a[3]), "r"(b0), "r"(b1));
}
static __device__ __forceinline__ uint32_t smem_u32(const void* p) {
    return (uint32_t)__cvta_generic_to_shared(p);
}
static __device__ __forceinline__ void cp4(uint32_t dst, const void* src, bool pred) {
    int sz = pred ? 4 : 0;
    asm volatile("cp.async.ca.shared.global [%0], [%1], 4, %2;\n"
                 :: "r"(dst), "l"(src), "r"(sz));
}
static __device__ __forceinline__ void cp16(uint32_t dst, const void* src) {
    asm volatile("cp.async.cg.shared.global [%0], [%1], 16;\n"
                 :: "r"(dst), "l"(src));
}
static __device__ __forceinline__ void cp_commit() {
    asm volatile("cp.async.commit_group;\n");
}
template<int N> static __device__ __forceinline__ void cp_wait() {
    asm volatile("cp.async.wait_group %0;\n" :: "n"(N));
}

// ---------------- S = I - (Dict^T Dict)/L, packed for mma B-frags ----------
// pair index p = kc*1024 + n*4 + t : (.x, .y) = (S[kc*8+t][n], S[kc*8+t+4][n])
__global__ void compute_S_kernel(const float* __restrict__ Dict,
                                 const float* __restrict__ Lp) {
    int i = blockIdx.x, j = threadIdx.x;     // i = k row, j = n col
    float L = *Lp;
    float g = 0.f;
#pragma unroll 8
    for (int c = 0; c < 64; c++) g += Dict[c*256 + i] * Dict[c*256 + j];
    float v = (i == j ? 1.f : 0.f) - g / L;
    int kc = i >> 3, r = i & 7;
    int t = r & 3, slot = r >> 2;
    g_Sp[(kc*1024 + j*4 + t)*2 + slot] = __uint_as_float(f2tf32(v));
}

// ---------------- 3x3 conv, pad 1, NCHW, tensor-core tf32, cp.async --------
// 16x16 spatial tile (N=256 px), 64 oc (M). 8 warps = 2(M) x 4(N).
// Double-buffered ic-chunks of 8 staged with cp.async overlapped with MMA.
// Weights staged in raw gmem order [oc][72] (pitch 76) via cp16.
#define C3_XS  2624                   // 8*328 floats per buffer
#define C3_WS  4864                   // 64*76 floats per buffer
#define CONV3_SMEM ((2*C3_XS + 2*C3_WS)*4)

template<int CIN, bool RELU_IN, bool RELU_OUT, bool BIAS>
__global__ __launch_bounds__(256, 2) void conv3x3_tc(
    const float* __restrict__ in, const float* __restrict__ w,
    const float* __restrict__ bias, float* __restrict__ out, int Cout)
{
    extern __shared__ __align__(16) float sm[];
    float* xsb = sm;                  // [2][8][18x18 pitch 328]
    float* wsb = sm + 2*C3_XS;        // [2][oc64][72 pitch 76]

    int b    = blockIdx.x >> 4;
    int tile = blockIdx.x & 15;
    int oy0  = (tile >> 2) << 4;
    int ox0  = (tile & 3) << 4;
    int ocBase = blockIdx.y << 6;

    int tid  = threadIdx.x;
    int lane = tid & 31, warp = tid >> 5;
    int wm = warp >> 2, wn = warp & 3;
    int g = lane >> 2, t = lane & 3;

    const int NCH = CIN / 8;

    float acc[2][8][4];
#pragma unroll
    for (int am = 0; am < 2; am++)
#pragma unroll
        for (int ng = 0; ng < 8; ng++)
#pragma unroll
            for (int j = 0; j < 4; j++) acc[am][ng][j] = 0.f;

    // stage chunk `ch` into buffer `bi`
    auto stage = [&](int ch, int bi) {
        int ic0 = ch << 3;
        float* xs = xsb + bi*C3_XS;
        float* ws = wsb + bi*C3_WS;
        for (int i = tid; i < 8*324; i += 256) {
            int ic = i / 324, rem = i - ic*324;
            int r = rem / 18, c = rem - r*18;
            int gy = oy0 - 1 + r, gx = ox0 - 1 + c;
            bool ok = ((unsigned)gy < 64u) && ((unsigned)gx < 64u);
            const float* src = ok
                ? in + (((size_t)(b*CIN + ic0 + ic))*64 + gy)*64 + gx
                : in;
            cp4(smem_u32(xs + ic*328 + rem), src, ok);
        }
        // weights: 72 contiguous floats per oc = 18 aligned 16B quads
        for (int i = tid; i < 64*18; i += 256) {
            int oc = i / 18, q = i - oc*18;
            cp16(smem_u32(ws + oc*76 + q*4),
                 w + ((size_t)(ocBase + oc)*CIN + ic0)*9 + q*4);
        }
        cp_commit();
    };

    stage(0, 0);
    for (int ch = 0; ch < NCH; ch++) {
        if (ch + 1 < NCH) { stage(ch + 1, (ch + 1) & 1); cp_wait<1>(); }
        else              { cp_wait<0>(); }
        __syncthreads();

        const float* xs = xsb + (ch & 1)*C3_XS;
        const float* ws = wsb + (ch & 1)*C3_WS;
#pragma unroll
        for (int kh = 0; kh < 3; kh++) {
#pragma unroll
            for (int kw = 0; kw < 3; kw++) {
                int tap = kh*3 + kw;
                uint32_t a[2][4];
#pragma unroll
                for (int am = 0; am < 2; am++) {
                    const float* wp = ws + (wm*32 + am*16)*76;
                    a[am][0] = __float_as_uint(wp[(g  )*76 + t*9 + tap]);
                    a[am][1] = __float_as_uint(wp[(g+8)*76 + t*9 + tap]);
                    a[am][2] = __float_as_uint(wp[(g  )*76 + t*9 + 36 + tap]);
                    a[am][3] = __float_as_uint(wp[(g+8)*76 + t*9 + 36 + tap]);
                }
#pragma unroll
                for (int ng = 0; ng < 8; ng++) {
                    int r  = (wn << 2) + (ng >> 1);
                    int c0 = (ng & 1) << 3;
                    const float* xp = xs + (r+kh)*18 + c0 + kw + g;
                    float v0 = xp[ t   *328];
                    float v1 = xp[(t+4)*328];
                    if (RELU_IN) { v0 = fmaxf(v0, 0.f); v1 = fmaxf(v1, 0.f); }
                    uint32_t b0 = __float_as_uint(v0);
                    uint32_t b1 = __float_as_uint(v1);
                    mma_tf32(acc[0][ng], a[0], b0, b1);
                    mma_tf32(acc[1][ng], a[1], b0, b1);
                }
            }
        }
        __syncthreads();
    }

#pragma unroll
    for (int am = 0; am < 2; am++) {
        int oc0 = ocBase + wm*32 + am*16 + g;
        float bv0 = BIAS ? bias[oc0]     : 0.f;
        float bv1 = BIAS ? bias[oc0 + 8] : 0.f;
#pragma unroll
        for (int ng = 0; ng < 8; ng++) {
            int r = (wn << 2) + (ng >> 1);
            int c = ((ng & 1) << 3) + 2*t;
            size_t o0 = ((size_t)(b*Cout + oc0)*64 + oy0 + r)*64 + ox0 + c;
            size_t o1 = o0 + (size_t)8*64*64;
            float r00 = acc[am][ng][0]+bv0, r01 = acc[am][ng][1]+bv0;
            float r10 = acc[am][ng][2]+bv1, r11 = acc[am][ng][3]+bv1;
            if (RELU_OUT) {
                r00 = fmaxf(r00, 0.f); r01 = fmaxf(r01, 0.f);
                r10 = fmaxf(r10, 0.f); r11 = fmaxf(r11, 0.f);
            }
            *(float2*)(out + o0) = make_float2(r00, r01);
            *(float2*)(out + o1) = make_float2(r10, r11);
        }
    }
}

// ---------------- 1x1 conv + residual add, tensor-core tf32, cp.async ------
// Input t is already relu'd by the producer. N=256 px, M=64 oc, K chunks 16.
__global__ __launch_bounds__(256) void conv1x1_res_tc(
    const float* __restrict__ t_, const float* __restrict__ w2,
    float* __restrict__ l)
{
    __shared__ __align__(16) float ts[2][16*264];  // [k16][px256 pitch 264]
    __shared__ __align__(16) float ws[2][64*20];   // [oc64][k16 pitch 20]

    int b   = blockIdx.x >> 4;
    int px0 = (blockIdx.x & 15) << 8;
    int ocBase = blockIdx.y << 6;
    int tid  = threadIdx.x;
    int lane = tid & 31, warp = tid >> 5;
    int wm = warp >> 2, wn = warp & 3;
    int g = lane >> 2, tt = lane & 3;

    float acc[2][8][4];
#pragma unroll
    for (int am = 0; am < 2; am++)
#pragma unroll
        for (int ng = 0; ng < 8; ng++)
#pragma unroll
            for (int j = 0; j < 4; j++) acc[am][ng][j] = 0.f;

    auto stage = [&](int ch, int bi) {
        int kc = ch << 4;
        for (int i = tid; i < 1024; i += 256) {
            int k = i >> 6, p4 = (i & 63) << 2;
            cp16(smem_u32(&ts[bi][k*264 + p4]),
                 t_ + ((size_t)(b*128 + kc + k))*4096 + px0 + p4);
        }
        {
            int i = tid;  // 256 = 64 oc x 4 quads
            int oc = i >> 2, kq = (i & 3) << 2;
            cp16(smem_u32(&ws[bi][oc*20 + kq]),
                 w2 + (size_t)(ocBase + oc)*128 + kc + kq);
        }
        cp_commit();
    };

    stage(0, 0);
    for (int ch = 0; ch < 8; ch++) {
        if (ch + 1 < 8) { stage(ch + 1, (ch + 1) & 1); cp_wait<1>(); }
        else            { cp_wait<0>(); }
        __syncthreads();

        const float* tsb = ts[ch & 1];
        const float* wsb = ws[ch & 1];
#pragma unroll
        for (int ks = 0; ks < 2; ks++) {
            int k0 = ks*8;
            uint32_t a[2][4];
#pragma unroll
            for (int am = 0; am < 2; am++) {
                const float* wp = wsb + (wm*32 + am*16)*20 + k0;
                a[am][0] = __float_as_uint(wp[(g  )*20 + tt]);
                a[am][1] = __float_as_uint(wp[(g+8)*20 + tt]);
                a[am][2] = __float_as_uint(wp[(g  )*20 + tt+4]);
                a[am][3] = __float_as_uint(wp[(g+8)*20 + tt+4]);
            }
#pragma unroll
            for (int ng = 0; ng < 8; ng++) {
                int n0 = wn*64 + ng*8;
                uint32_t b0 = __float_as_uint(tsb[(k0+tt  )*264 + n0 + g]);
                uint32_t b1 = __float_as_uint(tsb[(k0+tt+4)*264 + n0 + g]);
                mma_tf32(acc[0][ng], a[0], b0, b1);
                mma_tf32(acc[1][ng], a[1], b0, b1);
            }
        }
        __syncthreads();
    }

#pragma unroll
    for (int am = 0; am < 2; am++) {
        int oc0 = ocBase + wm*32 + am*16 + g;
#pragma unroll
        for (int ng = 0; ng < 8; ng++) {
            int p = px0 + wn*64 + ng*8 + 2*tt;
            size_t o0 = ((size_t)(b*256 + oc0))*4096 + p;
            size_t o1 = o0 + (size_t)8*4096;
            float2 v0 = *(float2*)(l + o0);
            float2 v1 = *(float2*)(l + o1);
            v0.x += acc[am][ng][0]; v0.y += acc[am][ng][1];
            v1.x += acc[am][ng][2]; v1.y += acc[am][ng][3];
            *(float2*)(l + o0) = v0;
            *(float2*)(l + o1) = v1;
        }
    }
}

// ---------------- channel attention: pooled reductions ---------------------
__global__ void pool_kernel() {
    int bc = blockIdx.x;
    const float* p = g_l + (size_t)bc*4096;
    int tid = threadIdx.x;
    float s = 0.f, m = -3.402823466e38f;
    for (int i = tid; i < 4096; i += 256) {
        float v = p[i];
        s += v; m = fmaxf(m, v);
    }
    __shared__ float ss[256], smx[256];
    ss[tid] = s; smx[tid] = m;
    __syncthreads();
    for (int st = 128; st > 0; st >>= 1) {
        if (tid < st) { ss[tid] += ss[tid+st]; smx[tid] = fmaxf(smx[tid], smx[tid+st]); }
        __syncthreads();
    }
    if (tid == 0) { g_avg[bc] = ss[0] * (1.f/4096.f); g_mx[bc] = smx[0]; }
}

// ---------------- channel attention MLP (tiny) -----------------------------
__global__ void camlp_kernel(const float* __restrict__ w1,
                             const float* __restrict__ w2) {
    int b = blockIdx.x;
    int tid = threadIdx.x;
    __shared__ float av[256], mv[256], ha[16], hm[16];
    av[tid] = g_avg[b*256 + tid];
    mv[tid] = g_mx[b*256 + tid];
    __syncthreads();
    if (tid < 16) {
        float sa = 0.f, sm_ = 0.f;
        for (int c = 0; c < 256; c++) {
            float wv = w1[tid*256 + c];
            sa  += av[c]*wv;
            sm_ += mv[c]*wv;
        }
        ha[tid] = fmaxf(sa, 0.f);
        hm[tid] = fmaxf(sm_, 0.f);
    }
    __syncthreads();
    float oa = 0.f, om = 0.f;
#pragma unroll
    for (int j = 0; j < 16; j++) {
        float wv = w2[tid*16 + j];
        oa += ha[j]*wv;
        om += hm[j]*wv;
    }
    g_catt[b*256 + tid] = sigmoidf_(oa + om);
}

// ---------------- spatial stats of channel-scaled l ------------------------
__global__ void spatial_stats_kernel() {
    int b   = blockIdx.x >> 4;
    int px  = ((blockIdx.x & 15) << 8) + threadIdx.x;
    __shared__ float ca[256];
    ca[threadIdx.x] = g_catt[b*256 + threadIdx.x];
    __syncthreads();
    float s = 0.f, m = -3.402823466e38f;
    for (int ch = 0; ch < 256; ch++) {
        float v = g_l[((size_t)(b*256 + ch))*4096 + px] * ca[ch];
        s += v; m = fmaxf(m, v);
    }
    g_s2[((size_t)(b*2 + 0))*4096 + px] = s * (1.f/256.f);
    g_s2[((size_t)(b*2 + 1))*4096 + px] = m;
}

// ---------------- spatial attention conv (2->1, 3x3, pad1) -----------------
__global__ void saconv_kernel(const float* __restrict__ saw) {
    int b  = blockIdx.x >> 4;
    int px = ((blockIdx.x & 15) << 8) + threadIdx.x;
    int py = px >> 6, pxx = px & 63;
    __shared__ float w[18];
    if (threadIdx.x < 18) w[threadIdx.x] = saw[threadIdx.x];
    __syncthreads();
    float a = 0.f;
#pragma unroll
    for (int ch = 0; ch < 2; ch++)
#pragma unroll
        for (int kh = 0; kh < 3; kh++)
#pragma unroll
            for (int kw = 0; kw < 3; kw++) {
                int gy = py - 1 + kh, gx = pxx - 1 + kw;
                if ((unsigned)gy < 64u && (unsigned)gx < 64u)
                    a += g_s2[((size_t)(b*2 + ch))*4096 + gy*64 + gx] * w[ch*9 + kh*3 + kw];
            }
    g_satt[b*4096 + px] = sigmoidf_(a);
}

// ---------------- LISTA persistent tensor-core kernel ----------------------
// S B-fragments stream from L2 via packed g_Sp (LDG.64, prefetch 1 kc ahead);
// the kc loop has NO barriers. Only 2 barriers/iteration around the epilogue.
#define ZS_OFF   0
#define YL_OFF   16640
#define LAM_OFF  33280
#define XSH_OFF  49920              // [64][68] init staging
#define DSH_OFF  16640              // aliases YL+LAM (epilogue only)
#define LISTA_SMEM ((49920 + 4352) * 4)

__global__ __launch_bounds__(256, 1) void lista_kernel(
    const float* __restrict__ x, const float* __restrict__ Dict,
    const float* __restrict__ Lp, const int* __restrict__ iterp,
    float* __restrict__ zOut, float* __restrict__ xrOut)
{
    extern __shared__ __align__(16) float smem[];
    float* zs  = smem + ZS_OFF;     // [64][260]
    float* yl  = smem + YL_OFF;     // [64][260]
    float* lam = smem + LAM_OFF;    // [64][260]
    float* xsh = smem + XSH_OFF;    // [64][68]

    int tid = threadIdx.x;
    int gp0 = blockIdx.x * 64;
    int b   = gp0 >> 12;
    int px0 = gp0 & 4095;
    float invL = 1.f / *Lp;
    int iters = *iterp;

    for (int i = tid; i < 4096; i += 256) {
        int c = i >> 6, p = i & 63;
        xsh[p*68 + c] = x[((size_t)(b*64 + c))*4096 + px0 + p];
    }
    for (int i = tid; i < 16384; i += 256) {
        int n = i >> 6, p = i & 63;
        float lv = g_l[((size_t)(b*256 + n))*4096 + px0 + p];
        lam[p*260 + n] = lv * g_catt[b*256 + n] * g_satt[b*4096 + px0 + p] * invL;
    }
    __syncthreads();

    {
        int n0 = tid & 63;
        int pg = tid >> 6;
        float acc[16][4];
#pragma unroll
        for (int p = 0; p < 16; p++)
#pragma unroll
            for (int j = 0; j < 4; j++) acc[p][j] = 0.f;
        for (int c = 0; c < 64; c++) {
            float d0 = Dict[c*256 + n0];
            float d1 = Dict[c*256 + n0 + 64];
            float d2 = Dict[c*256 + n0 + 128];
            float d3 = Dict[c*256 + n0 + 192];
#pragma unroll
            for (int p = 0; p < 16; p++) {
                float xv = xsh[(pg*16 + p)*68 + c];
                acc[p][0] += xv*d0;
                acc[p][1] += xv*d1;
                acc[p][2] += xv*d2;
                acc[p][3] += xv*d3;
            }
        }
#pragma unroll
        for (int p = 0; p < 16; p++)
#pragma unroll
            for (int j = 0; j < 4; j++) {
                int idx = (pg*16 + p)*260 + n0 + 64*j;
                yl[idx] = acc[p][j]*invL;
                zs[idx] = softt(acc[p][j], lam[idx]);
            }
    }
    __syncthreads();

    const int lane = tid & 31;
    const int warp = tid >> 5;
    const int wm   = warp >> 2;
    const int wn   = warp & 3;
    const int g    = lane >> 2;
    const int t    = lane & 3;
    const int mBase = wm*32;
    const int nBase = wn*64;

    const float2* Sp = (const float2*)g_Sp;
    // per-lane fragment gather base: pair idx = kc*1024 + n*4 + t
    int fOff[8];
#pragma unroll
    for (int nt = 0; nt < 8; nt++) fOff[nt] = (nBase + nt*8 + g)*4 + t;

    float2 bA[8], bB[8];
    // preload kc=0 (stays primed across iterations: kc=31 prefetches kc=0)
#pragma unroll
    for (int nt = 0; nt < 8; nt++) bA[nt] = __ldg(Sp + fOff[nt]);

    float acc[2][8][4];

    auto kstep = [&](int kc, float2 (&bcur)[8], float2 (&bnxt)[8]) {
        int kcn = (kc + 1) & 31;
        const float2* sp = Sp + kcn*1024;
#pragma unroll
        for (int nt = 0; nt < 8; nt++) bnxt[nt] = __ldg(sp + fOff[nt]);
        int k0 = kc*8;
        uint32_t a[2][4];
#pragma unroll
        for (int am = 0; am < 2; am++) {
            int row = mBase + am*16 + g;
            a[am][0] = f2tf32(zs[row*260 + k0 + t]);
            a[am][1] = f2tf32(zs[(row+8)*260 + k0 + t]);
            a[am][2] = f2tf32(zs[row*260 + k0 + t + 4]);
            a[am][3] = f2tf32(zs[(row+8)*260 + k0 + t + 4]);
        }
#pragma unroll
        for (int nt = 0; nt < 8; nt++) {
            uint32_t b0 = __float_as_uint(bcur[nt].x);
            uint32_t b1 = __float_as_uint(bcur[nt].y);
            mma_tf32(acc[0][nt], a[0], b0, b1);
            mma_tf32(acc[1][nt], a[1], b0, b1);
        }
    };

    for (int it = 0; it < iters; it++) {
#pragma unroll
        for (int am = 0; am < 2; am++)
#pragma unroll
            for (int nt = 0; nt < 8; nt++)
#pragma unroll
                for (int j = 0; j < 4; j++) acc[am][nt][j] = 0.f;

        for (int kc = 0; kc < 32; kc += 2) {
            kstep(kc,     bA, bB);
            kstep(kc + 1, bB, bA);
        }
        __syncthreads();   // all A-frag reads of zs complete

#pragma unroll
        for (int am = 0; am < 2; am++) {
#pragma unroll
            for (int nt = 0; nt < 8; nt++) {
                int row = mBase + am*16 + g;
                int col = nBase + nt*8 + 2*t;
                int i0 = row*260 + col;
                int i1 = (row+8)*260 + col;
                zs[i0]   = softt(acc[am][nt][0] + yl[i0],   lam[i0]);
                zs[i0+1] = softt(acc[am][nt][1] + yl[i0+1], lam[i0+1]);
                zs[i1]   = softt(acc[am][nt][2] + yl[i1],   lam[i1]);
                zs[i1+1] = softt(acc[am][nt][3] + yl[i1+1], lam[i1+1]);
            }
        }
        __syncthreads();
    }

    for (int i = tid; i < 16384; i += 256) {
        int n = i >> 6, p = i & 63;
        zOut[((size_t)(b*256 + n))*4096 + px0 + p] = zs[p*260 + n];
    }
    __syncthreads();

    float* dsh = smem + DSH_OFF;
    for (int i = tid; i < 16384; i += 256) {
        int c = i >> 8, a = i & 255;
        dsh[a*68 + c] = Dict[c*256 + a];
    }
    __syncthreads();

    {
        int p = tid & 63, cg = tid >> 6;
        float acc2[16];
#pragma unroll
        for (int j = 0; j < 16; j++) acc2[j] = 0.f;
        for (int a = 0; a < 256; a++) {
            float zv = zs[p*260 + a];
            const float4* dr = (const float4*)&dsh[a*68 + cg*16];
            float4 d0 = dr[0], d1 = dr[1], d2 = dr[2], d3 = dr[3];
            acc2[0]  += zv*d0.x; acc2[1]  += zv*d0.y; acc2[2]  += zv*d0.z; acc2[3]  += zv*d0.w;
            acc2[4]  += zv*d1.x; acc2[5]  += zv*d1.y; acc2[6]  += zv*d1.z; acc2[7]  += zv*d1.w;
            acc2[8]  += zv*d2.x; acc2[9]  += zv*d2.y; acc2[10] += zv*d2.z; acc2[11] += zv*d2.w;
            acc2[12] += zv*d3.x; acc2[13] += zv*d3.y; acc2[14] += zv*d3.z; acc2[15] += zv*d3.w;
        }
#pragma unroll
        for (int j = 0; j < 16; j++)
            xrOut[((size_t)(b*64 + cg*16 + j))*4096 + px0 + p] = acc2[j];
    }
}

// ---------------- launch ----------------------------------------------------
extern "C" void kernel_launch(void* const* d_in, const int* in_sizes, int n_in,
                              void* d_out, int out_size)
{
    const float* x      = (const float*)d_in[0];
    const float* conv_w = (const float*)d_in[1];
    const float* conv_b = (const float*)d_in[2];
    const float* r1w1   = (const float*)d_in[3];
    const float* r1w2   = (const float*)d_in[4];
    const float* r2w1   = (const float*)d_in[5];
    const float* r2w2   = (const float*)d_in[6];
    const float* caw1   = (const float*)d_in[7];
    const float* caw2   = (const float*)d_in[8];
    const float* saw    = (const float*)d_in[9];
    const float* Dict   = (const float*)d_in[10];
    const float* Lp     = (const float*)d_in[11];
    const int*   itp    = (const int*)d_in[12];

    float* out   = (float*)d_out;
    float* zOut  = out;
    float* xrOut = out + (size_t)8*256*4096;
    float* dOut  = xrOut + (size_t)8*64*4096;

    float *lp, *tp;
    cudaGetSymbolAddress((void**)&lp, g_l);
    cudaGetSymbolAddress((void**)&tp, g_t);

    cudaFuncSetAttribute((const void*)conv3x3_tc<64, false, false, true>,
                         cudaFuncAttributeMaxDynamicSharedMemorySize, CONV3_SMEM);
    cudaFuncSetAttribute((const void*)conv3x3_tc<256, true, true, false>,
                         cudaFuncAttributeMaxDynamicSharedMemorySize, CONV3_SMEM);
    cudaFuncSetAttribute((const void*)lista_kernel,
                         cudaFuncAttributeMaxDynamicSharedMemorySize, LISTA_SMEM);

    compute_S_kernel<<<256, 256>>>(Dict, Lp);

    conv3x3_tc<64, false, false, true><<<dim3(128, 4), 256, CONV3_SMEM>>>(
        x, conv_w, conv_b, lp, 256);

    conv3x3_tc<256, true, true, false><<<dim3(128, 2), 256, CONV3_SMEM>>>(
        lp, r1w1, nullptr, tp, 128);
    conv1x1_res_tc<<<dim3(128, 4), 256>>>(tp, r1w2, lp);

    conv3x3_tc<256, true, true, false><<<dim3(128, 2), 256, CONV3_SMEM>>>(
        lp, r2w1, nullptr, tp, 128);
    conv1x1_res_tc<<<dim3(128, 4), 256>>>(tp, r2w2, lp);

    pool_kernel<<<2048, 256>>>();
    camlp_kernel<<<8, 256>>>(caw1, caw2);
    spatial_stats_kernel<<<128, 256>>>();
    saconv_kernel<<<128, 256>>>(saw);

    lista_kernel<<<512, 256, LISTA_SMEM>>>(x, Dict, Lp, itp, zOut, xrOut);

    cudaMemcpyAsync(dOut, Dict, (size_t)64*256*sizeof(float), cudaMemcpyDeviceToDevice);
}

// round 15
// speedup vs baseline: 4.0617x; 1.3276x over previous
#include <cuda_runtime.h>
#include <cuda_bf16.h>
#include <math.h>
#include <stdint.h>

// ---------------- scratch (device globals; no allocation allowed) ----------
__device__ float    g_l[8*256*64*64];      // encoder feature map l (fp32, raw)
__device__ float    g_Sp[256*256];         // LISTA matrix, mma-fragment-packed
__device__ uint32_t g_xpk[8*32*4096];      // x packed bf16 pairs
__device__ uint32_t g_lpk[8*128*4096];     // relu(l) packed bf16 pairs
__device__ uint32_t g_tpk[8*64*4096];      // relu(t) packed bf16 pairs
__device__ uint32_t g_w3a[9*256*32];       // conv1 w packed   [tap][oc][ic/2]
__device__ uint32_t g_w3b1[9*128*128];     // res1 w1 packed
__device__ uint32_t g_w3b2[9*128*128];     // res2 w1 packed
__device__ uint32_t g_w1a[256*64];         // res1 w2 packed   [oc][k/2]
__device__ uint32_t g_w1b[256*64];         // res2 w2 packed
__device__ float    g_avg[8*256];
__device__ float    g_mx[8*256];
__device__ float    g_catt[8*256];
__device__ float    g_s2[8*2*64*64];
__device__ float    g_satt[8*64*64];

static __device__ __forceinline__ float softt(float v, float la) {
    float a = fabsf(v) - la;
    a = a > 0.f ? a : 0.f;
    return copysignf(a, v);
}
static __device__ __forceinline__ float sigmoidf_(float v) {
    return 1.f / (1.f + expf(-v));
}
static __device__ __forceinline__ uint32_t f2tf32(float f) {
    uint32_t r;
    asm("cvt.rna.tf32.f32 %0, %1;" : "=r"(r) : "f"(f));
    return r;
}
static __device__ __forceinline__ uint32_t packbf2(float a, float b) {
    __nv_bfloat162 h = __floats2bfloat162_rn(a, b);
    return *(uint32_t*)&h;
}
static __device__ __forceinline__ void mma_tf32(float* c, const uint32_t* a,
                                                uint32_t b0, uint32_t b1) {
    asm volatile(
        "mma.sync.aligned.m16n8k8.row.col.f32.tf32.tf32.f32 "
        "{%0,%1,%2,%3}, {%4,%5,%6,%7}, {%8,%9}, {%0,%1,%2,%3};\n"
        : "+f"(c[0]), "+f"(c[1]), "+f"(c[2]), "+f"(c[3])
        : "r"(a[0]), "r"(a[1]), "r"(a[2]), "r"(a[3]), "r"(b0), "r"(b1));
}
static __device__ __forceinline__ void mma_bf16(float* c, const uint32_t* a,
                                                uint32_t b0, uint32_t b1) {
    asm volatile(
        "mma.sync.aligned.m16n8k16.row.col.f32.bf16.bf16.f32 "
        "{%0,%1,%2,%3}, {%4,%5,%6,%7}, {%8,%9}, {%0,%1,%2,%3};\n"
        : "+f"(c[0]), "+f"(c[1]), "+f"(c[2]), "+f"(c[3])
        : "r"(a[0]), "r"(a[1]), "r"(a[2]), "r"(a[3]), "r"(b0), "r"(b1));
}
static __device__ __forceinline__ uint32_t smem_u32(const void* p) {
    return (uint32_t)__cvta_generic_to_shared(p);
}
static __device__ __forceinline__ void cp4(uint32_t dst, const void* src, bool pred) {
    int sz = pred ? 4 : 0;
    asm volatile("cp.async.ca.shared.global [%0], [%1], 4, %2;\n"
                 :: "r"(dst), "l"(src), "r"(sz));
}
static __device__ __forceinline__ void cp16(uint32_t dst, const void* src) {
    asm volatile("cp.async.cg.shared.global [%0], [%1], 16;\n"
                 :: "r"(dst), "l"(src));
}
static __device__ __forceinline__ void cp_commit() {
    asm volatile("cp.async.commit_group;\n");
}
template<int N> static __device__ __forceinline__ void cp_wait() {
    asm volatile("cp.async.wait_group %0;\n" :: "n"(N));
}

// ---------------- S = I - (Dict^T Dict)/L, packed for mma B-frags ----------
__global__ void compute_S_kernel(const float* __restrict__ Dict,
                                 const float* __restrict__ Lp) {
    int i = blockIdx.x, j = threadIdx.x;     // i = k row, j = n col
    float L = *Lp;
    float g = 0.f;
#pragma unroll 8
    for (int c = 0; c < 64; c++) g += Dict[c*256 + i] * Dict[c*256 + j];
    float v = (i == j ? 1.f : 0.f) - g / L;
    int kc = i >> 3, r = i & 7;
    int t = r & 3, slot = r >> 2;
    g_Sp[(kc*1024 + j*4 + t)*2 + slot] = __uint_as_float(f2tf32(v));
}

// ---------------- pack kernels (fp32 -> bf16 channel-pair u32) -------------
// src plane-pair (2q, 2q+1) -> dst plane q.  Used for x.
__global__ void pack_pairs_kernel(const float* __restrict__ src,
                                  uint32_t* __restrict__ dst, int totalU32) {
    int i = blockIdx.x*256 + threadIdx.x;
    if (i >= totalU32) return;
    int q = i >> 12, px = i & 4095;
    float v0 = src[((size_t)(2*q))*4096 + px];
    float v1 = src[((size_t)(2*q+1))*4096 + px];
    dst[i] = packbf2(v0, v1);
}
// OIHW 3x3 weights -> [tap][oc][ic/2]
__global__ void pack_w3_kernel(const float* __restrict__ w,
                               uint32_t* __restrict__ dst, int Cin, int Cout) {
    int i = blockIdx.x*256 + threadIdx.x;
    int C2 = Cin >> 1;
    int total = 9*Cout*C2;
    if (i >= total) return;
    int tap = i / (Cout*C2);
    int rem = i - tap*Cout*C2;
    int oc = rem / C2, pr = rem - oc*C2;
    float v0 = w[((size_t)oc*Cin + 2*pr  )*9 + tap];
    float v1 = w[((size_t)oc*Cin + 2*pr+1)*9 + tap];
    dst[i] = packbf2(v0, v1);
}
// [oc][128] 1x1 weights -> [oc][64]
__global__ void pack_w1_kernel(const float* __restrict__ w,
                               uint32_t* __restrict__ dst) {
    int i = blockIdx.x*256 + threadIdx.x;   // 256*64 total
    int oc = i >> 6, pr = i & 63;
    dst[i] = packbf2(w[oc*128 + 2*pr], w[oc*128 + 2*pr + 1]);
}

// ---------------- 3x3 conv, pad 1, bf16 m16n8k16 tensor cores --------------
// 16x16 spatial tile (N=256 px), 64 oc (M). 8 warps = 2(M) x 4(N).
// ic chunks of 16 (8 bf16 pairs), double-buffered cp.async.
// Outputs: optional raw fp32 (+bias) and relu'd bf16 pair-packed (shfl pack).
#define C3_XS  2624                   // 8*328 u32 per buffer
#define C3_WS  6912                   // 9*64*12 u32 per buffer
#define CONV3_SMEM ((2*C3_XS + 2*C3_WS)*4)

template<int CIN, bool OUT_F32, bool BIAS>
__global__ __launch_bounds__(256, 2) void conv3x3_bf16(
    const uint32_t* __restrict__ apk,   // [b][CIN/2][4096]
    const uint32_t* __restrict__ wpk,   // [tap][oc][CIN/2]
    const float* __restrict__ bias,
    float* __restrict__ outf,           // [b][Cout][4096] raw
    uint32_t* __restrict__ outpk,       // [b][Cout/2][4096] relu packed
    int Cout)
{
    extern __shared__ __align__(16) uint32_t sm[];
    uint32_t* xsb = sm;                 // [2][8 pr][18x18 pitch 328]
    uint32_t* wsb = sm + 2*C3_XS;       // [2][tap][oc64][pr pitch 12]

    int b    = blockIdx.x >> 4;
    int tile = blockIdx.x & 15;
    int oy0  = (tile >> 2) << 4;
    int ox0  = (tile & 3) << 4;
    int ocBase = blockIdx.y << 6;

    int tid  = threadIdx.x;
    int lane = tid & 31, warp = tid >> 5;
    int wm = warp >> 2, wn = warp & 3;
    int g = lane >> 2, t = lane & 3;

    const int C2  = CIN >> 1;
    const int NCH = CIN >> 4;           // 16 ic per chunk

    float acc[2][8][4];
#pragma unroll
    for (int am = 0; am < 2; am++)
#pragma unroll
        for (int ng = 0; ng < 8; ng++)
#pragma unroll
            for (int j = 0; j < 4; j++) acc[am][ng][j] = 0.f;

    auto stage = [&](int ch, int bi) {
        int pr0 = ch << 3;
        uint32_t* xs = xsb + bi*C3_XS;
        uint32_t* ws = wsb + bi*C3_WS;
        for (int i = tid; i < 8*324; i += 256) {
            int pp = i / 324, rem = i - pp*324;
            int r = rem / 18, c = rem - r*18;
            int gy = oy0 - 1 + r, gx = ox0 - 1 + c;
            bool ok = ((unsigned)gy < 64u) && ((unsigned)gx < 64u);
            const uint32_t* src = ok
                ? apk + ((size_t)(b*C2 + pr0 + pp))*4096 + gy*64 + gx
                : apk;
            cp4(smem_u32(xs + pp*328 + rem), src, ok);
        }
        for (int i = tid; i < 9*64*2; i += 256) {
            int to = i >> 1, half = i & 1;     // to = tap*64 + oc
            int tap = to >> 6, oc = to & 63;
            cp16(smem_u32(ws + to*12 + half*4),
                 wpk + ((size_t)(tap*Cout + ocBase + oc))*C2 + pr0 + half*4);
        }
        cp_commit();
    };

    stage(0, 0);
    for (int ch = 0; ch < NCH; ch++) {
        if (ch + 1 < NCH) { stage(ch + 1, (ch + 1) & 1); cp_wait<1>(); }
        else              { cp_wait<0>(); }
        __syncthreads();

        const uint32_t* xs = xsb + (ch & 1)*C3_XS;
        const uint32_t* ws = wsb + (ch & 1)*C3_WS;
#pragma unroll
        for (int kh = 0; kh < 3; kh++) {
#pragma unroll
            for (int kw = 0; kw < 3; kw++) {
                int tap = kh*3 + kw;
                uint32_t a[2][4];
#pragma unroll
                for (int am = 0; am < 2; am++) {
                    const uint32_t* wp = ws + tap*768 + (wm*32 + am*16)*12;
                    a[am][0] = wp[(g  )*12 + t];
                    a[am][1] = wp[(g+8)*12 + t];
                    a[am][2] = wp[(g  )*12 + t+4];
                    a[am][3] = wp[(g+8)*12 + t+4];
                }
#pragma unroll
                for (int ng = 0; ng < 8; ng++) {
                    int r  = (wn << 2) + (ng >> 1);
                    int c0 = (ng & 1) << 3;
                    const uint32_t* xp = xs + (r+kh)*18 + c0 + kw + g;
                    uint32_t b0 = xp[ t   *328];
                    uint32_t b1 = xp[(t+4)*328];
                    mma_bf16(acc[0][ng], a[0], b0, b1);
                    mma_bf16(acc[1][ng], a[1], b0, b1);
                }
            }
        }
        __syncthreads();
    }

    int C2o = Cout >> 1;
#pragma unroll
    for (int am = 0; am < 2; am++) {
        int oc0 = ocBase + wm*32 + am*16 + g;
        float bv0 = BIAS ? bias[oc0]     : 0.f;
        float bv1 = BIAS ? bias[oc0 + 8] : 0.f;
#pragma unroll
        for (int ng = 0; ng < 8; ng++) {
            int r = (wn << 2) + (ng >> 1);
            int c = ((ng & 1) << 3) + 2*t;
            float r00 = acc[am][ng][0]+bv0, r01 = acc[am][ng][1]+bv0;
            float r10 = acc[am][ng][2]+bv1, r11 = acc[am][ng][3]+bv1;
            if (OUT_F32) {
                size_t o0 = ((size_t)(b*Cout + oc0)*64 + oy0 + r)*64 + ox0 + c;
                size_t o1 = o0 + (size_t)8*64*64;
                *(float2*)(outf + o0) = make_float2(r00, r01);
                *(float2*)(outf + o1) = make_float2(r10, r11);
            }
            // relu + shfl pack: lane (g,t) pairs with lane (g+1,t) = lane+4
            float p0 = fmaxf(r00, 0.f), p1 = fmaxf(r01, 0.f);
            float p2 = fmaxf(r10, 0.f), p3 = fmaxf(r11, 0.f);
            float q0 = __shfl_down_sync(0xffffffffu, p0, 4);
            float q1 = __shfl_down_sync(0xffffffffu, p1, 4);
            float q2 = __shfl_down_sync(0xffffffffu, p2, 4);
            float q3 = __shfl_down_sync(0xffffffffu, p3, 4);
            if ((g & 1) == 0) {
                int ocp = oc0 >> 1;
                size_t base = ((size_t)(b*C2o + ocp))*4096 + (oy0 + r)*64 + ox0 + c;
                uint2 w0 = make_uint2(packbf2(p0, q0), packbf2(p1, q1));
                uint2 w1 = make_uint2(packbf2(p2, q2), packbf2(p3, q3));
                *(uint2*)(outpk + base)                    = w0;
                *(uint2*)(outpk + base + (size_t)4*4096)   = w1;
            }
        }
    }
}

// ---------------- 1x1 conv + residual add, bf16 m16n8k16 -------------------
// Input tpk already relu'd+packed. K=128 in chunks of 16 (8 pairs).
template<bool PACK>
__global__ __launch_bounds__(256) void conv1x1_bf16(
    const uint32_t* __restrict__ tpk,   // [b][64][4096]
    const uint32_t* __restrict__ wpk,   // [oc256][64]
    float* __restrict__ l,              // in/out fp32
    uint32_t* __restrict__ lpk_out)     // [b][128][4096] relu packed
{
    __shared__ __align__(16) uint32_t ts[2][8*264];   // [pr][px256 pitch 264]
    __shared__ __align__(16) uint32_t ws[2][64*12];   // [oc][pr pitch 12]

    int b   = blockIdx.x >> 4;
    int px0 = (blockIdx.x & 15) << 8;
    int ocBase = blockIdx.y << 6;
    int tid  = threadIdx.x;
    int lane = tid & 31, warp = tid >> 5;
    int wm = warp >> 2, wn = warp & 3;
    int g = lane >> 2, tt = lane & 3;

    float acc[2][8][4];
#pragma unroll
    for (int am = 0; am < 2; am++)
#pragma unroll
        for (int ng = 0; ng < 8; ng++)
#pragma unroll
            for (int j = 0; j < 4; j++) acc[am][ng][j] = 0.f;

    auto stage = [&](int ch, int bi) {
        int pr0 = ch << 3;
        for (int i = tid; i < 512; i += 256) {
            int pp = i >> 6, p4 = (i & 63) << 2;
            cp16(smem_u32(&ts[bi][pp*264 + p4]),
                 tpk + ((size_t)(b*64 + pr0 + pp))*4096 + px0 + p4);
        }
        if (tid < 128) {
            int oc = tid >> 1, half = tid & 1;
            cp16(smem_u32(&ws[bi][oc*12 + half*4]),
                 wpk + (size_t)(ocBase + oc)*64 + pr0 + half*4);
        }
        cp_commit();
    };

    stage(0, 0);
    for (int ch = 0; ch < 8; ch++) {
        if (ch + 1 < 8) { stage(ch + 1, (ch + 1) & 1); cp_wait<1>(); }
        else            { cp_wait<0>(); }
        __syncthreads();

        const uint32_t* tsb = ts[ch & 1];
        const uint32_t* wsb = ws[ch & 1];
        uint32_t a[2][4];
#pragma unroll
        for (int am = 0; am < 2; am++) {
            const uint32_t* wp = wsb + (wm*32 + am*16)*12;
            a[am][0] = wp[(g  )*12 + tt];
            a[am][1] = wp[(g+8)*12 + tt];
            a[am][2] = wp[(g  )*12 + tt+4];
            a[am][3] = wp[(g+8)*12 + tt+4];
        }
#pragma unroll
        for (int ng = 0; ng < 8; ng++) {
            int n0 = wn*64 + ng*8;
            uint32_t b0 = tsb[(tt  )*264 + n0 + g];
            uint32_t b1 = tsb[(tt+4)*264 + n0 + g];
            mma_bf16(acc[0][ng], a[0], b0, b1);
            mma_bf16(acc[1][ng], a[1], b0, b1);
        }
        __syncthreads();
    }

#pragma unroll
    for (int am = 0; am < 2; am++) {
        int oc0 = ocBase + wm*32 + am*16 + g;
#pragma unroll
        for (int ng = 0; ng < 8; ng++) {
            int p = px0 + wn*64 + ng*8 + 2*tt;
            size_t o0 = ((size_t)(b*256 + oc0))*4096 + p;
            size_t o1 = o0 + (size_t)8*4096;
            float2 v0 = *(float2*)(l + o0);
            float2 v1 = *(float2*)(l + o1);
            v0.x += acc[am][ng][0]; v0.y += acc[am][ng][1];
            v1.x += acc[am][ng][2]; v1.y += acc[am][ng][3];
            *(float2*)(l + o0) = v0;
            *(float2*)(l + o1) = v1;
            if (PACK) {
                float p0 = fmaxf(v0.x, 0.f), p1 = fmaxf(v0.y, 0.f);
                float p2 = fmaxf(v1.x, 0.f), p3 = fmaxf(v1.y, 0.f);
                float q0 = __shfl_down_sync(0xffffffffu, p0, 4);
                float q1 = __shfl_down_sync(0xffffffffu, p1, 4);
                float q2 = __shfl_down_sync(0xffffffffu, p2, 4);
                float q3 = __shfl_down_sync(0xffffffffu, p3, 4);
                if ((g & 1) == 0) {
                    int ocp = oc0 >> 1;
                    size_t base = ((size_t)(b*128 + ocp))*4096 + p;
                    *(uint2*)(lpk_out + base) =
                        make_uint2(packbf2(p0, q0), packbf2(p1, q1));
                    *(uint2*)(lpk_out + base + (size_t)4*4096) =
                        make_uint2(packbf2(p2, q2), packbf2(p3, q3));
                }
            }
        }
    }
}

// ---------------- channel attention: pooled reductions ---------------------
__global__ void pool_kernel() {
    int bc = blockIdx.x;
    const float* p = g_l + (size_t)bc*4096;
    int tid = threadIdx.x;
    float s = 0.f, m = -3.402823466e38f;
    for (int i = tid; i < 4096; i += 256) {
        float v = p[i];
        s += v; m = fmaxf(m, v);
    }
    __shared__ float ss[256], smx[256];
    ss[tid] = s; smx[tid] = m;
    __syncthreads();
    for (int st = 128; st > 0; st >>= 1) {
        if (tid < st) { ss[tid] += ss[tid+st]; smx[tid] = fmaxf(smx[tid], smx[tid+st]); }
        __syncthreads();
    }
    if (tid == 0) { g_avg[bc] = ss[0] * (1.f/4096.f); g_mx[bc] = smx[0]; }
}

// ---------------- channel attention MLP (tiny) -----------------------------
__global__ void camlp_kernel(const float* __restrict__ w1,
                             const float* __restrict__ w2) {
    int b = blockIdx.x;
    int tid = threadIdx.x;
    __shared__ float av[256], mv[256], ha[16], hm[16];
    av[tid] = g_avg[b*256 + tid];
    mv[tid] = g_mx[b*256 + tid];
    __syncthreads();
    if (tid < 16) {
        float sa = 0.f, sm_ = 0.f;
        for (int c = 0; c < 256; c++) {
            float wv = w1[tid*256 + c];
            sa  += av[c]*wv;
            sm_ += mv[c]*wv;
        }
        ha[tid] = fmaxf(sa, 0.f);
        hm[tid] = fmaxf(sm_, 0.f);
    }
    __syncthreads();
    float oa = 0.f, om = 0.f;
#pragma unroll
    for (int j = 0; j < 16; j++) {
        float wv = w2[tid*16 + j];
        oa += ha[j]*wv;
        om += hm[j]*wv;
    }
    g_catt[b*256 + tid] = sigmoidf_(oa + om);
}

// ---------------- spatial stats of channel-scaled l ------------------------
__global__ void spatial_stats_kernel() {
    int b   = blockIdx.x >> 4;
    int px  = ((blockIdx.x & 15) << 8) + threadIdx.x;
    __shared__ float ca[256];
    ca[threadIdx.x] = g_catt[b*256 + threadIdx.x];
    __syncthreads();
    float s = 0.f, m = -3.402823466e38f;
    for (int ch = 0; ch < 256; ch++) {
        float v = g_l[((size_t)(b*256 + ch))*4096 + px] * ca[ch];
        s += v; m = fmaxf(m, v);
    }
    g_s2[((size_t)(b*2 + 0))*4096 + px] = s * (1.f/256.f);
    g_s2[((size_t)(b*2 + 1))*4096 + px] = m;
}

// ---------------- spatial attention conv (2->1, 3x3, pad1) -----------------
__global__ void saconv_kernel(const float* __restrict__ saw) {
    int b  = blockIdx.x >> 4;
    int px = ((blockIdx.x & 15) << 8) + threadIdx.x;
    int py = px >> 6, pxx = px & 63;
    __shared__ float w[18];
    if (threadIdx.x < 18) w[threadIdx.x] = saw[threadIdx.x];
    __syncthreads();
    float a = 0.f;
#pragma unroll
    for (int ch = 0; ch < 2; ch++)
#pragma unroll
        for (int kh = 0; kh < 3; kh++)
#pragma unroll
            for (int kw = 0; kw < 3; kw++) {
                int gy = py - 1 + kh, gx = pxx - 1 + kw;
                if ((unsigned)gy < 64u && (unsigned)gx < 64u)
                    a += g_s2[((size_t)(b*2 + ch))*4096 + gy*64 + gx] * w[ch*9 + kh*3 + kw];
            }
    g_satt[b*4096 + px] = sigmoidf_(a);
}

// ---------------- LISTA persistent tensor-core kernel ----------------------
// S streamed from L2 (packed g_Sp, LDG.64, 1-kc-ahead prefetch); barrier-free
// kc loop. z stored pre-rounded to tf32 in smem (exact on final iteration).
#define ZS_OFF   0
#define YL_OFF   16640
#define LAM_OFF  33280
#define XSH_OFF  49920
#define DSH_OFF  16640
#define LISTA_SMEM ((49920 + 4352) * 4)

__global__ __launch_bounds__(256, 1) void lista_kernel(
    const float* __restrict__ x, const float* __restrict__ Dict,
    const float* __restrict__ Lp, const int* __restrict__ iterp,
    float* __restrict__ zOut, float* __restrict__ xrOut)
{
    extern __shared__ __align__(16) float smem[];
    float* zs  = smem + ZS_OFF;     // [64][260]
    float* yl  = smem + YL_OFF;     // [64][260]
    float* lam = smem + LAM_OFF;    // [64][260]
    float* xsh = smem + XSH_OFF;    // [64][68]

    int tid = threadIdx.x;
    int gp0 = blockIdx.x * 64;
    int b   = gp0 >> 12;
    int px0 = gp0 & 4095;
    float invL = 1.f / *Lp;
    int iters = *iterp;

    for (int i = tid; i < 4096; i += 256) {
        int c = i >> 6, p = i & 63;
        xsh[p*68 + c] = x[((size_t)(b*64 + c))*4096 + px0 + p];
    }
    for (int i = tid; i < 16384; i += 256) {
        int n = i >> 6, p = i & 63;
        float lv = g_l[((size_t)(b*256 + n))*4096 + px0 + p];
        lam[p*260 + n] = lv * g_catt[b*256 + n] * g_satt[b*4096 + px0 + p] * invL;
    }
    __syncthreads();

    {
        int n0 = tid & 63;
        int pg = tid >> 6;
        float acc[16][4];
#pragma unroll
        for (int p = 0; p < 16; p++)
#pragma unroll
            for (int j = 0; j < 4; j++) acc[p][j] = 0.f;
        for (int c = 0; c < 64; c++) {
            float d0 = Dict[c*256 + n0];
            float d1 = Dict[c*256 + n0 + 64];
            float d2 = Dict[c*256 + n0 + 128];
            float d3 = Dict[c*256 + n0 + 192];
#pragma unroll
            for (int p = 0; p < 16; p++) {
                float xv = xsh[(pg*16 + p)*68 + c];
                acc[p][0] += xv*d0;
                acc[p][1] += xv*d1;
                acc[p][2] += xv*d2;
                acc[p][3] += xv*d3;
            }
        }
#pragma unroll
        for (int p = 0; p < 16; p++)
#pragma unroll
            for (int j = 0; j < 4; j++) {
                int idx = (pg*16 + p)*260 + n0 + 64*j;
                yl[idx] = acc[p][j]*invL;
                float z0 = softt(acc[p][j], lam[idx]);
                zs[idx] = (iters == 0) ? z0 : __uint_as_float(f2tf32(z0));
            }
    }
    __syncthreads();

    const int lane = tid & 31;
    const int warp = tid >> 5;
    const int wm   = warp >> 2;
    const int wn   = warp & 3;
    const int g    = lane >> 2;
    const int t    = lane & 3;
    const int mBase = wm*32;
    const int nBase = wn*64;

    const float2* Sp = (const float2*)g_Sp;
    int fOff[8];
#pragma unroll
    for (int nt = 0; nt < 8; nt++) fOff[nt] = (nBase + nt*8 + g)*4 + t;

    float2 bA[8], bB[8];
#pragma unroll
    for (int nt = 0; nt < 8; nt++) bA[nt] = __ldg(Sp + fOff[nt]);

    float acc[2][8][4];

    auto kstep = [&](int kc, float2 (&bcur)[8], float2 (&bnxt)[8]) {
        int kcn = (kc + 1) & 31;
        const float2* sp = Sp + kcn*1024;
#pragma unroll
        for (int nt = 0; nt < 8; nt++) bnxt[nt] = __ldg(sp + fOff[nt]);
        int k0 = kc*8;
        uint32_t a[2][4];
#pragma unroll
        for (int am = 0; am < 2; am++) {
            int row = mBase + am*16 + g;
            a[am][0] = __float_as_uint(zs[row*260 + k0 + t]);
            a[am][1] = __float_as_uint(zs[(row+8)*260 + k0 + t]);
            a[am][2] = __float_as_uint(zs[row*260 + k0 + t + 4]);
            a[am][3] = __float_as_uint(zs[(row+8)*260 + k0 + t + 4]);
        }
#pragma unroll
        for (int nt = 0; nt < 8; nt++) {
            uint32_t b0 = __float_as_uint(bcur[nt].x);
            uint32_t b1 = __float_as_uint(bcur[nt].y);
            mma_tf32(acc[0][nt], a[0], b0, b1);
            mma_tf32(acc[1][nt], a[1], b0, b1);
        }
    };

    for (int it = 0; it < iters; it++) {
        bool last = (it == iters - 1);
#pragma unroll
        for (int am = 0; am < 2; am++)
#pragma unroll
            for (int nt = 0; nt < 8; nt++)
#pragma unroll
                for (int j = 0; j < 4; j++) acc[am][nt][j] = 0.f;

        for (int kc = 0; kc < 32; kc += 2) {
            kstep(kc,     bA, bB);
            kstep(kc + 1, bB, bA);
        }
        __syncthreads();

#pragma unroll
        for (int am = 0; am < 2; am++) {
#pragma unroll
            for (int nt = 0; nt < 8; nt++) {
                int row = mBase + am*16 + g;
                int col = nBase + nt*8 + 2*t;
                int i0 = row*260 + col;
                int i1 = (row+8)*260 + col;
                float z0 = softt(acc[am][nt][0] + yl[i0],   lam[i0]);
                float z1 = softt(acc[am][nt][1] + yl[i0+1], lam[i0+1]);
                float z2 = softt(acc[am][nt][2] + yl[i1],   lam[i1]);
                float z3 = softt(acc[am][nt][3] + yl[i1+1], lam[i1+1]);
                zs[i0]   = last ? z0 : __uint_as_float(f2tf32(z0));
                zs[i0+1] = last ? z1 : __uint_as_float(f2tf32(z1));
                zs[i1]   = last ? z2 : __uint_as_float(f2tf32(z2));
                zs[i1+1] = last ? z3 : __uint_as_float(f2tf32(z3));
            }
        }
        __syncthreads();
    }

    for (int i = tid; i < 16384; i += 256) {
        int n = i >> 6, p = i & 63;
        zOut[((size_t)(b*256 + n))*4096 + px0 + p] = zs[p*260 + n];
    }
    __syncthreads();

    float* dsh = smem + DSH_OFF;
    for (int i = tid; i < 16384; i += 256) {
        int c = i >> 8, a = i & 255;
        dsh[a*68 + c] = Dict[c*256 + a];
    }
    __syncthreads();

    {
        int p = tid & 63, cg = tid >> 6;
        float acc2[16];
#pragma unroll
        for (int j = 0; j < 16; j++) acc2[j] = 0.f;
        for (int a = 0; a < 256; a++) {
            float zv = zs[p*260 + a];
            const float4* dr = (const float4*)&dsh[a*68 + cg*16];
            float4 d0 = dr[0], d1 = dr[1], d2 = dr[2], d3 = dr[3];
            acc2[0]  += zv*d0.x; acc2[1]  += zv*d0.y; acc2[2]  += zv*d0.z; acc2[3]  += zv*d0.w;
            acc2[4]  += zv*d1.x; acc2[5]  += zv*d1.y; acc2[6]  += zv*d1.z; acc2[7]  += zv*d1.w;
            acc2[8]  += zv*d2.x; acc2[9]  += zv*d2.y; acc2[10] += zv*d2.z; acc2[11] += zv*d2.w;
            acc2[12] += zv*d3.x; acc2[13] += zv*d3.y; acc2[14] += zv*d3.z; acc2[15] += zv*d3.w;
        }
#pragma unroll
        for (int j = 0; j < 16; j++)
            xrOut[((size_t)(b*64 + cg*16 + j))*4096 + px0 + p] = acc2[j];
    }
}

// ---------------- launch ----------------------------------------------------
extern "C" void kernel_launch(void* const* d_in, const int* in_sizes, int n_in,
                              void* d_out, int out_size)
{
    const float* x      = (const float*)d_in[0];
    const float* conv_w = (const float*)d_in[1];
    const float* conv_b = (const float*)d_in[2];
    const float* r1w1   = (const float*)d_in[3];
    const float* r1w2   = (const float*)d_in[4];
    const float* r2w1   = (const float*)d_in[5];
    const float* r2w2   = (const float*)d_in[6];
    const float* caw1   = (const float*)d_in[7];
    const float* caw2   = (const float*)d_in[8];
    const float* saw    = (const float*)d_in[9];
    const float* Dict   = (const float*)d_in[10];
    const float* Lp     = (const float*)d_in[11];
    const int*   itp    = (const int*)d_in[12];

    float* out   = (float*)d_out;
    float* zOut  = out;
    float* xrOut = out + (size_t)8*256*4096;
    float* dOut  = xrOut + (size_t)8*64*4096;

    float *lp;
    uint32_t *xpk, *lpk, *tpk, *w3a, *w3b1, *w3b2, *w1a, *w1b;
    cudaGetSymbolAddress((void**)&lp,   g_l);
    cudaGetSymbolAddress((void**)&xpk,  g_xpk);
    cudaGetSymbolAddress((void**)&lpk,  g_lpk);
    cudaGetSymbolAddress((void**)&tpk,  g_tpk);
    cudaGetSymbolAddress((void**)&w3a,  g_w3a);
    cudaGetSymbolAddress((void**)&w3b1, g_w3b1);
    cudaGetSymbolAddress((void**)&w3b2, g_w3b2);
    cudaGetSymbolAddress((void**)&w1a,  g_w1a);
    cudaGetSymbolAddress((void**)&w1b,  g_w1b);

    cudaFuncSetAttribute((const void*)conv3x3_bf16<64, true, true>,
                         cudaFuncAttributeMaxDynamicSharedMemorySize, CONV3_SMEM);
    cudaFuncSetAttribute((const void*)conv3x3_bf16<256, false, false>,
                         cudaFuncAttributeMaxDynamicSharedMemorySize, CONV3_SMEM);
    cudaFuncSetAttribute((const void*)lista_kernel,
                         cudaFuncAttributeMaxDynamicSharedMemorySize, LISTA_SMEM);

    compute_S_kernel<<<256, 256>>>(Dict, Lp);

    // pack inputs + weights to bf16 pairs
    pack_pairs_kernel<<<4096, 256>>>(x, xpk, 8*32*4096);
    pack_w3_kernel<<<288, 256>>>(conv_w, w3a, 64, 256);
    pack_w3_kernel<<<576, 256>>>(r1w1, w3b1, 256, 128);
    pack_w3_kernel<<<576, 256>>>(r2w1, w3b2, 256, 128);
    pack_w1_kernel<<<64, 256>>>(r1w2, w1a);
    pack_w1_kernel<<<64, 256>>>(r2w2, w1b);

    // encoder
    conv3x3_bf16<64, true, true><<<dim3(128, 4), 256, CONV3_SMEM>>>(
        xpk, w3a, conv_b, lp, lpk, 256);

    conv3x3_bf16<256, false, false><<<dim3(128, 2), 256, CONV3_SMEM>>>(
        lpk, w3b1, nullptr, nullptr, tpk, 128);
    conv1x1_bf16<true><<<dim3(128, 4), 256>>>(tpk, w1a, lp, lpk);

    conv3x3_bf16<256, false, false><<<dim3(128, 2), 256, CONV3_SMEM>>>(
        lpk, w3b2, nullptr, nullptr, tpk, 128);
    conv1x1_bf16<false><<<dim3(128, 4), 256>>>(tpk, w1b, lp, nullptr);

    // CBAM attention
    pool_kernel<<<2048, 256>>>();
    camlp_kernel<<<8, 256>>>(caw1, caw2);
    spatial_stats_kernel<<<128, 256>>>();
    saconv_kernel<<<128, 256>>>(saw);

    // LISTA
    lista_kernel<<<512, 256, LISTA_SMEM>>>(x, Dict, Lp, itp, zOut, xrOut);

    cudaMemcpyAsync(dOut, Dict, (size_t)64*256*sizeof(float), cudaMemcpyDeviceToDevice);
}

// round 16
// speedup vs baseline: 4.2623x; 1.0494x over previous
#include <cuda_runtime.h>
#include <cuda_bf16.h>
#include <math.h>
#include <stdint.h>

// ---------------- scratch (device globals; no allocation allowed) ----------
__device__ float    g_l[8*256*64*64];      // encoder feature map l (fp32, raw)
__device__ float    g_D1p[64*256];         // Dict^T B-frags for GEMM1 (tf32)
__device__ float    g_D2p[64*256];         // Dict/L B-frags for GEMM2 (tf32)
__device__ uint32_t g_xpk[8*32*4096];      // x packed bf16 pairs
__device__ uint32_t g_lpk[8*128*4096];     // relu(l) packed bf16 pairs
__device__ uint32_t g_tpk[8*64*4096];      // relu(t) packed bf16 pairs
__device__ uint32_t g_w3a[9*256*32];       // conv1 w packed   [tap][oc][ic/2]
__device__ uint32_t g_w3b1[9*128*128];     // res1 w1 packed
__device__ uint32_t g_w3b2[9*128*128];     // res2 w1 packed
__device__ uint32_t g_w1a[256*64];         // res1 w2 packed   [oc][k/2]
__device__ uint32_t g_w1b[256*64];         // res2 w2 packed
__device__ float    g_avg[8*256];
__device__ float    g_mx[8*256];
__device__ float    g_catt[8*256];
__device__ float    g_s2[8*2*64*64];
__device__ float    g_satt[8*64*64];

static __device__ __forceinline__ float softt(float v, float la) {
    float a = fabsf(v) - la;
    a = a > 0.f ? a : 0.f;
    return copysignf(a, v);
}
static __device__ __forceinline__ float sigmoidf_(float v) {
    return 1.f / (1.f + expf(-v));
}
static __device__ __forceinline__ uint32_t f2tf32(float f) {
    uint32_t r;
    asm("cvt.rna.tf32.f32 %0, %1;" : "=r"(r) : "f"(f));
    return r;
}
static __device__ __forceinline__ uint32_t packbf2(float a, float b) {
    __nv_bfloat162 h = __floats2bfloat162_rn(a, b);
    return *(uint32_t*)&h;
}
static __device__ __forceinline__ void mma_tf32(float* c, const uint32_t* a,
                                                uint32_t b0, uint32_t b1) {
    asm volatile(
        "mma.sync.aligned.m16n8k8.row.col.f32.tf32.tf32.f32 "
        "{%0,%1,%2,%3}, {%4,%5,%6,%7}, {%8,%9}, {%0,%1,%2,%3};\n"
        : "+f"(c[0]), "+f"(c[1]), "+f"(c[2]), "+f"(c[3])
        : "r"(a[0]), "r"(a[1]), "r"(a[2]), "r"(a[3]), "r"(b0), "r"(b1));
}
static __device__ __forceinline__ void mma_bf16(float* c, const uint32_t* a,
                                                uint32_t b0, uint32_t b1) {
    asm volatile(
        "mma.sync.aligned.m16n8k16.row.col.f32.bf16.bf16.f32 "
        "{%0,%1,%2,%3}, {%4,%5,%6,%7}, {%8,%9}, {%0,%1,%2,%3};\n"
        : "+f"(c[0]), "+f"(c[1]), "+f"(c[2]), "+f"(c[3])
        : "r"(a[0]), "r"(a[1]), "r"(a[2]), "r"(a[3]), "r"(b0), "r"(b1));
}
static __device__ __forceinline__ uint32_t smem_u32(const void* p) {
    return (uint32_t)__cvta_generic_to_shared(p);
}
static __device__ __forceinline__ void cp4(uint32_t dst, const void* src, bool pred) {
    int sz = pred ? 4 : 0;
    asm volatile("cp.async.ca.shared.global [%0], [%1], 4, %2;\n"
                 :: "r"(dst), "l"(src), "r"(sz));
}
static __device__ __forceinline__ void cp16(uint32_t dst, const void* src) {
    asm volatile("cp.async.cg.shared.global [%0], [%1], 16;\n"
                 :: "r"(dst), "l"(src));
}
static __device__ __forceinline__ void cp_commit() {
    asm volatile("cp.async.commit_group;\n");
}
template<int N> static __device__ __forceinline__ void cp_wait() {
    asm volatile("cp.async.wait_group %0;\n" :: "n"(N));
}

// ---------------- Dict fragment packing for factorized LISTA ---------------
// GEMM1: u = z @ Dict^T.  B[k=a][n=c] = Dict[c][a].
// pair idx = kc*256 + n*4 + t  -> (.x,.y) = (Dict[n][kc*8+t], Dict[n][kc*8+t+4])
__global__ void pack_D1_kernel(const float* __restrict__ Dict) {
    int i = blockIdx.x*256 + threadIdx.x;      // 8192 pairs
    int kc = i >> 8, rem = i & 255;
    int n = rem >> 2, t = rem & 3;
    float2* dst = (float2*)g_D1p;
    float2 v;
    v.x = __uint_as_float(f2tf32(Dict[n*256 + kc*8 + t]));
    v.y = __uint_as_float(f2tf32(Dict[n*256 + kc*8 + t + 4]));
    dst[i] = v;
}
// GEMM2: corr = u @ (Dict/L).  B[k=c][n=a] = Dict[c][a]/L.
// pair idx = kc*1024 + n*4 + t -> (Dict[kc*8+t][n]/L, Dict[kc*8+t+4][n]/L)
__global__ void pack_D2_kernel(const float* __restrict__ Dict,
                               const float* __restrict__ Lp) {
    int i = blockIdx.x*256 + threadIdx.x;      // 8192 pairs
    float invL = 1.f / *Lp;
    int kc = i >> 10, rem = i & 1023;
    int n = rem >> 2, t = rem & 3;
    float2* dst = (float2*)g_D2p;
    float2 v;
    v.x = __uint_as_float(f2tf32(Dict[(kc*8 + t    )*256 + n] * invL));
    v.y = __uint_as_float(f2tf32(Dict[(kc*8 + t + 4)*256 + n] * invL));
    dst[i] = v;
}

// ---------------- pack kernels (fp32 -> bf16 channel-pair u32) -------------
__global__ void pack_pairs_kernel(const float* __restrict__ src,
                                  uint32_t* __restrict__ dst, int totalU32) {
    int i = blockIdx.x*256 + threadIdx.x;
    if (i >= totalU32) return;
    int q = i >> 12, px = i & 4095;
    float v0 = src[((size_t)(2*q))*4096 + px];
    float v1 = src[((size_t)(2*q+1))*4096 + px];
    dst[i] = packbf2(v0, v1);
}
__global__ void pack_w3_kernel(const float* __restrict__ w,
                               uint32_t* __restrict__ dst, int Cin, int Cout) {
    int i = blockIdx.x*256 + threadIdx.x;
    int C2 = Cin >> 1;
    int total = 9*Cout*C2;
    if (i >= total) return;
    int tap = i / (Cout*C2);
    int rem = i - tap*Cout*C2;
    int oc = rem / C2, pr = rem - oc*C2;
    float v0 = w[((size_t)oc*Cin + 2*pr  )*9 + tap];
    float v1 = w[((size_t)oc*Cin + 2*pr+1)*9 + tap];
    dst[i] = packbf2(v0, v1);
}
__global__ void pack_w1_kernel(const float* __restrict__ w,
                               uint32_t* __restrict__ dst) {
    int i = blockIdx.x*256 + threadIdx.x;   // 256*64 total
    int oc = i >> 6, pr = i & 63;
    dst[i] = packbf2(w[oc*128 + 2*pr], w[oc*128 + 2*pr + 1]);
}

// ---------------- 3x3 conv, pad 1, bf16 m16n8k16 tensor cores --------------
#define C3_XS  2624                   // 8*328 u32 per buffer
#define C3_WS  6912                   // 9*64*12 u32 per buffer
#define CONV3_SMEM ((2*C3_XS + 2*C3_WS)*4)

template<int CIN, bool OUT_F32, bool BIAS>
__global__ __launch_bounds__(256, 2) void conv3x3_bf16(
    const uint32_t* __restrict__ apk,   // [b][CIN/2][4096]
    const uint32_t* __restrict__ wpk,   // [tap][oc][CIN/2]
    const float* __restrict__ bias,
    float* __restrict__ outf,           // [b][Cout][4096] raw
    uint32_t* __restrict__ outpk,       // [b][Cout/2][4096] relu packed
    int Cout)
{
    extern __shared__ __align__(16) uint32_t sm[];
    uint32_t* xsb = sm;                 // [2][8 pr][18x18 pitch 328]
    uint32_t* wsb = sm + 2*C3_XS;       // [2][tap][oc64][pr pitch 12]

    int b    = blockIdx.x >> 4;
    int tile = blockIdx.x & 15;
    int oy0  = (tile >> 2) << 4;
    int ox0  = (tile & 3) << 4;
    int ocBase = blockIdx.y << 6;

    int tid  = threadIdx.x;
    int lane = tid & 31, warp = tid >> 5;
    int wm = warp >> 2, wn = warp & 3;
    int g = lane >> 2, t = lane & 3;

    const int C2  = CIN >> 1;
    const int NCH = CIN >> 4;

    float acc[2][8][4];
#pragma unroll
    for (int am = 0; am < 2; am++)
#pragma unroll
        for (int ng = 0; ng < 8; ng++)
#pragma unroll
            for (int j = 0; j < 4; j++) acc[am][ng][j] = 0.f;

    auto stage = [&](int ch, int bi) {
        int pr0 = ch << 3;
        uint32_t* xs = xsb + bi*C3_XS;
        uint32_t* ws = wsb + bi*C3_WS;
        for (int i = tid; i < 8*324; i += 256) {
            int pp = i / 324, rem = i - pp*324;
            int r = rem / 18, c = rem - r*18;
            int gy = oy0 - 1 + r, gx = ox0 - 1 + c;
            bool ok = ((unsigned)gy < 64u) && ((unsigned)gx < 64u);
            const uint32_t* src = ok
                ? apk + ((size_t)(b*C2 + pr0 + pp))*4096 + gy*64 + gx
                : apk;
            cp4(smem_u32(xs + pp*328 + rem), src, ok);
        }
        for (int i = tid; i < 9*64*2; i += 256) {
            int to = i >> 1, half = i & 1;
            int tap = to >> 6, oc = to & 63;
            cp16(smem_u32(ws + to*12 + half*4),
                 wpk + ((size_t)(tap*Cout + ocBase + oc))*C2 + pr0 + half*4);
        }
        cp_commit();
    };

    stage(0, 0);
    for (int ch = 0; ch < NCH; ch++) {
        if (ch + 1 < NCH) { stage(ch + 1, (ch + 1) & 1); cp_wait<1>(); }
        else              { cp_wait<0>(); }
        __syncthreads();

        const uint32_t* xs = xsb + (ch & 1)*C3_XS;
        const uint32_t* ws = wsb + (ch & 1)*C3_WS;
#pragma unroll
        for (int kh = 0; kh < 3; kh++) {
#pragma unroll
            for (int kw = 0; kw < 3; kw++) {
                int tap = kh*3 + kw;
                uint32_t a[2][4];
#pragma unroll
                for (int am = 0; am < 2; am++) {
                    const uint32_t* wp = ws + tap*768 + (wm*32 + am*16)*12;
                    a[am][0] = wp[(g  )*12 + t];
                    a[am][1] = wp[(g+8)*12 + t];
                    a[am][2] = wp[(g  )*12 + t+4];
                    a[am][3] = wp[(g+8)*12 + t+4];
                }
#pragma unroll
                for (int ng = 0; ng < 8; ng++) {
                    int r  = (wn << 2) + (ng >> 1);
                    int c0 = (ng & 1) << 3;
                    const uint32_t* xp = xs + (r+kh)*18 + c0 + kw + g;
                    uint32_t b0 = xp[ t   *328];
                    uint32_t b1 = xp[(t+4)*328];
                    mma_bf16(acc[0][ng], a[0], b0, b1);
                    mma_bf16(acc[1][ng], a[1], b0, b1);
                }
            }
        }
        __syncthreads();
    }

    int C2o = Cout >> 1;
#pragma unroll
    for (int am = 0; am < 2; am++) {
        int oc0 = ocBase + wm*32 + am*16 + g;
        float bv0 = BIAS ? bias[oc0]     : 0.f;
        float bv1 = BIAS ? bias[oc0 + 8] : 0.f;
#pragma unroll
        for (int ng = 0; ng < 8; ng++) {
            int r = (wn << 2) + (ng >> 1);
            int c = ((ng & 1) << 3) + 2*t;
            float r00 = acc[am][ng][0]+bv0, r01 = acc[am][ng][1]+bv0;
            float r10 = acc[am][ng][2]+bv1, r11 = acc[am][ng][3]+bv1;
            if (OUT_F32) {
                size_t o0 = ((size_t)(b*Cout + oc0)*64 + oy0 + r)*64 + ox0 + c;
                size_t o1 = o0 + (size_t)8*64*64;
                *(float2*)(outf + o0) = make_float2(r00, r01);
                *(float2*)(outf + o1) = make_float2(r10, r11);
            }
            float p0 = fmaxf(r00, 0.f), p1 = fmaxf(r01, 0.f);
            float p2 = fmaxf(r10, 0.f), p3 = fmaxf(r11, 0.f);
            float q0 = __shfl_down_sync(0xffffffffu, p0, 4);
            float q1 = __shfl_down_sync(0xffffffffu, p1, 4);
            float q2 = __shfl_down_sync(0xffffffffu, p2, 4);
            float q3 = __shfl_down_sync(0xffffffffu, p3, 4);
            if ((g & 1) == 0) {
                int ocp = oc0 >> 1;
                size_t base = ((size_t)(b*C2o + ocp))*4096 + (oy0 + r)*64 + ox0 + c;
                uint2 w0 = make_uint2(packbf2(p0, q0), packbf2(p1, q1));
                uint2 w1 = make_uint2(packbf2(p2, q2), packbf2(p3, q3));
                *(uint2*)(outpk + base)                    = w0;
                *(uint2*)(outpk + base + (size_t)4*4096)   = w1;
            }
        }
    }
}

// ---------------- 1x1 conv + residual add, bf16 m16n8k16 -------------------
template<bool PACK>
__global__ __launch_bounds__(256) void conv1x1_bf16(
    const uint32_t* __restrict__ tpk,   // [b][64][4096]
    const uint32_t* __restrict__ wpk,   // [oc256][64]
    float* __restrict__ l,              // in/out fp32
    uint32_t* __restrict__ lpk_out)     // [b][128][4096] relu packed
{
    __shared__ __align__(16) uint32_t ts[2][8*264];
    __shared__ __align__(16) uint32_t ws[2][64*12];

    int b   = blockIdx.x >> 4;
    int px0 = (blockIdx.x & 15) << 8;
    int ocBase = blockIdx.y << 6;
    int tid  = threadIdx.x;
    int lane = tid & 31, warp = tid >> 5;
    int wm = warp >> 2, wn = warp & 3;
    int g = lane >> 2, tt = lane & 3;

    float acc[2][8][4];
#pragma unroll
    for (int am = 0; am < 2; am++)
#pragma unroll
        for (int ng = 0; ng < 8; ng++)
#pragma unroll
            for (int j = 0; j < 4; j++) acc[am][ng][j] = 0.f;

    auto stage = [&](int ch, int bi) {
        int pr0 = ch << 3;
        for (int i = tid; i < 512; i += 256) {
            int pp = i >> 6, p4 = (i & 63) << 2;
            cp16(smem_u32(&ts[bi][pp*264 + p4]),
                 tpk + ((size_t)(b*64 + pr0 + pp))*4096 + px0 + p4);
        }
        if (tid < 128) {
            int oc = tid >> 1, half = tid & 1;
            cp16(smem_u32(&ws[bi][oc*12 + half*4]),
                 wpk + (size_t)(ocBase + oc)*64 + pr0 + half*4);
        }
        cp_commit();
    };

    stage(0, 0);
    for (int ch = 0; ch < 8; ch++) {
        if (ch + 1 < 8) { stage(ch + 1, (ch + 1) & 1); cp_wait<1>(); }
        else            { cp_wait<0>(); }
        __syncthreads();

        const uint32_t* tsb = ts[ch & 1];
        const uint32_t* wsb = ws[ch & 1];
        uint32_t a[2][4];
#pragma unroll
        for (int am = 0; am < 2; am++) {
            const uint32_t* wp = wsb + (wm*32 + am*16)*12;
            a[am][0] = wp[(g  )*12 + tt];
            a[am][1] = wp[(g+8)*12 + tt];
            a[am][2] = wp[(g  )*12 + tt+4];
            a[am][3] = wp[(g+8)*12 + tt+4];
        }
#pragma unroll
        for (int ng = 0; ng < 8; ng++) {
            int n0 = wn*64 + ng*8;
            uint32_t b0 = tsb[(tt  )*264 + n0 + g];
            uint32_t b1 = tsb[(tt+4)*264 + n0 + g];
            mma_bf16(acc[0][ng], a[0], b0, b1);
            mma_bf16(acc[1][ng], a[1], b0, b1);
        }
        __syncthreads();
    }

#pragma unroll
    for (int am = 0; am < 2; am++) {
        int oc0 = ocBase + wm*32 + am*16 + g;
#pragma unroll
        for (int ng = 0; ng < 8; ng++) {
            int p = px0 + wn*64 + ng*8 + 2*tt;
            size_t o0 = ((size_t)(b*256 + oc0))*4096 + p;
            size_t o1 = o0 + (size_t)8*4096;
            float2 v0 = *(float2*)(l + o0);
            float2 v1 = *(float2*)(l + o1);
            v0.x += acc[am][ng][0]; v0.y += acc[am][ng][1];
            v1.x += acc[am][ng][2]; v1.y += acc[am][ng][3];
            *(float2*)(l + o0) = v0;
            *(float2*)(l + o1) = v1;
            if (PACK) {
                float p0 = fmaxf(v0.x, 0.f), p1 = fmaxf(v0.y, 0.f);
                float p2 = fmaxf(v1.x, 0.f), p3 = fmaxf(v1.y, 0.f);
                float q0 = __shfl_down_sync(0xffffffffu, p0, 4);
                float q1 = __shfl_down_sync(0xffffffffu, p1, 4);
                float q2 = __shfl_down_sync(0xffffffffu, p2, 4);
                float q3 = __shfl_down_sync(0xffffffffu, p3, 4);
                if ((g & 1) == 0) {
                    int ocp = oc0 >> 1;
                    size_t base = ((size_t)(b*128 + ocp))*4096 + p;
                    *(uint2*)(lpk_out + base) =
                        make_uint2(packbf2(p0, q0), packbf2(p1, q1));
                    *(uint2*)(lpk_out + base + (size_t)4*4096) =
                        make_uint2(packbf2(p2, q2), packbf2(p3, q3));
                }
            }
        }
    }
}

// ---------------- channel attention: pooled reductions ---------------------
__global__ void pool_kernel() {
    int bc = blockIdx.x;
    const float* p = g_l + (size_t)bc*4096;
    int tid = threadIdx.x;
    float s = 0.f, m = -3.402823466e38f;
    for (int i = tid; i < 4096; i += 256) {
        float v = p[i];
        s += v; m = fmaxf(m, v);
    }
    __shared__ float ss[256], smx[256];
    ss[tid] = s; smx[tid] = m;
    __syncthreads();
    for (int st = 128; st > 0; st >>= 1) {
        if (tid < st) { ss[tid] += ss[tid+st]; smx[tid] = fmaxf(smx[tid], smx[tid+st]); }
        __syncthreads();
    }
    if (tid == 0) { g_avg[bc] = ss[0] * (1.f/4096.f); g_mx[bc] = smx[0]; }
}

// ---------------- channel attention MLP (tiny) -----------------------------
__global__ void camlp_kernel(const float* __restrict__ w1,
                             const float* __restrict__ w2) {
    int b = blockIdx.x;
    int tid = threadIdx.x;
    __shared__ float av[256], mv[256], ha[16], hm[16];
    av[tid] = g_avg[b*256 + tid];
    mv[tid] = g_mx[b*256 + tid];
    __syncthreads();
    if (tid < 16) {
        float sa = 0.f, sm_ = 0.f;
        for (int c = 0; c < 256; c++) {
            float wv = w1[tid*256 + c];
            sa  += av[c]*wv;
            sm_ += mv[c]*wv;
        }
        ha[tid] = fmaxf(sa, 0.f);
        hm[tid] = fmaxf(sm_, 0.f);
    }
    __syncthreads();
    float oa = 0.f, om = 0.f;
#pragma unroll
    for (int j = 0; j < 16; j++) {
        float wv = w2[tid*16 + j];
        oa += ha[j]*wv;
        om += hm[j]*wv;
    }
    g_catt[b*256 + tid] = sigmoidf_(oa + om);
}

// ---------------- spatial stats of channel-scaled l ------------------------
__global__ void spatial_stats_kernel() {
    int b   = blockIdx.x >> 4;
    int px  = ((blockIdx.x & 15) << 8) + threadIdx.x;
    __shared__ float ca[256];
    ca[threadIdx.x] = g_catt[b*256 + threadIdx.x];
    __syncthreads();
    float s = 0.f, m = -3.402823466e38f;
    for (int ch = 0; ch < 256; ch++) {
        float v = g_l[((size_t)(b*256 + ch))*4096 + px] * ca[ch];
        s += v; m = fmaxf(m, v);
    }
    g_s2[((size_t)(b*2 + 0))*4096 + px] = s * (1.f/256.f);
    g_s2[((size_t)(b*2 + 1))*4096 + px] = m;
}

// ---------------- spatial attention conv (2->1, 3x3, pad1) -----------------
__global__ void saconv_kernel(const float* __restrict__ saw) {
    int b  = blockIdx.x >> 4;
    int px = ((blockIdx.x & 15) << 8) + threadIdx.x;
    int py = px >> 6, pxx = px & 63;
    __shared__ float w[18];
    if (threadIdx.x < 18) w[threadIdx.x] = saw[threadIdx.x];
    __syncthreads();
    float a = 0.f;
#pragma unroll
    for (int ch = 0; ch < 2; ch++)
#pragma unroll
        for (int kh = 0; kh < 3; kh++)
#pragma unroll
            for (int kw = 0; kw < 3; kw++) {
                int gy = py - 1 + kh, gx = pxx - 1 + kw;
                if ((unsigned)gy < 64u && (unsigned)gx < 64u)
                    a += g_s2[((size_t)(b*2 + ch))*4096 + gy*64 + gx] * w[ch*9 + kh*3 + kw];
            }
    g_satt[b*4096 + px] = sigmoidf_(a);
}

// ---------------- LISTA persistent tensor-core kernel (rank-64) ------------
// z@S + y/L = z - ((z@Dict^T)@Dict)/L + y/L  (G = Dict^T Dict has rank 64).
// GEMM1: u = z@Dict^T  (N=64, K=256);  GEMM2: corr = u@(Dict/L) (N=256, K=64).
// Dict frags stream from L2; 2 barriers/iter; u lives in the xsh region.
#define ZS_OFF   0
#define YL_OFF   16640
#define LAM_OFF  33280
#define XSH_OFF  49920              // [64][68]: x at init, u in mainloop
#define DSH_OFF  16640
#define LISTA_SMEM ((49920 + 4352) * 4)

__global__ __launch_bounds__(256, 1) void lista_kernel(
    const float* __restrict__ x, const float* __restrict__ Dict,
    const float* __restrict__ Lp, const int* __restrict__ iterp,
    float* __restrict__ zOut, float* __restrict__ xrOut)
{
    extern __shared__ __align__(16) float smem[];
    float* zs  = smem + ZS_OFF;     // [64][260]
    float* yl  = smem + YL_OFF;     // [64][260]
    float* lam = smem + LAM_OFF;    // [64][260]
    float* xsh = smem + XSH_OFF;    // [64][68]  (x, then u)

    int tid = threadIdx.x;
    int gp0 = blockIdx.x * 64;
    int b   = gp0 >> 12;
    int px0 = gp0 & 4095;
    float invL = 1.f / *Lp;
    int iters = *iterp;

    for (int i = tid; i < 4096; i += 256) {
        int c = i >> 6, p = i & 63;
        xsh[p*68 + c] = x[((size_t)(b*64 + c))*4096 + px0 + p];
    }
    for (int i = tid; i < 16384; i += 256) {
        int n = i >> 6, p = i & 63;
        float lv = g_l[((size_t)(b*256 + n))*4096 + px0 + p];
        lam[p*260 + n] = lv * g_catt[b*256 + n] * g_satt[b*4096 + px0 + p] * invL;
    }
    __syncthreads();

    {
        int n0 = tid & 63;
        int pg = tid >> 6;
        float acc[16][4];
#pragma unroll
        for (int p = 0; p < 16; p++)
#pragma unroll
            for (int j = 0; j < 4; j++) acc[p][j] = 0.f;
        for (int c = 0; c < 64; c++) {
            float d0 = Dict[c*256 + n0];
            float d1 = Dict[c*256 + n0 + 64];
            float d2 = Dict[c*256 + n0 + 128];
            float d3 = Dict[c*256 + n0 + 192];
#pragma unroll
            for (int p = 0; p < 16; p++) {
                float xv = xsh[(pg*16 + p)*68 + c];
                acc[p][0] += xv*d0;
                acc[p][1] += xv*d1;
                acc[p][2] += xv*d2;
                acc[p][3] += xv*d3;
            }
        }
#pragma unroll
        for (int p = 0; p < 16; p++)
#pragma unroll
            for (int j = 0; j < 4; j++) {
                int idx = (pg*16 + p)*260 + n0 + 64*j;
                yl[idx] = acc[p][j]*invL;
                float z0 = softt(acc[p][j], lam[idx]);
                zs[idx] = (iters == 0) ? z0 : __uint_as_float(f2tf32(z0));
            }
    }
    __syncthreads();   // also: xsh (x) dead from here, reused as u

    const int lane = tid & 31;
    const int warp = tid >> 5;
    const int wm   = warp >> 2;
    const int wn   = warp & 3;
    const int g    = lane >> 2;
    const int t    = lane & 3;
    const int mBase = wm*32;
    const int nBase = wn*64;
    float* u = xsh;

    const float2* D1 = (const float2*)g_D1p;
    const float2* D2 = (const float2*)g_D2p;
    int f1[2], f2[8];
#pragma unroll
    for (int nt = 0; nt < 2; nt++) f1[nt] = (wn*16 + nt*8 + g)*4 + t;
#pragma unroll
    for (int nt = 0; nt < 8; nt++) f2[nt] = (nBase + nt*8 + g)*4 + t;

    float2 b1A[2], b1B[2], b2A[8], b2B[8];
#pragma unroll
    for (int nt = 0; nt < 2; nt++) b1A[nt] = __ldg(D1 + f1[nt]);
#pragma unroll
    for (int nt = 0; nt < 8; nt++) b2A[nt] = __ldg(D2 + f2[nt]);

    float acc1[2][2][4];
    float acc2[2][8][4];

    // GEMM1 kstep: K=256 in 32 chunks; A from zs, B from D1 (wraps mod 32)
    auto kstep1 = [&](int kc, float2 (&bc)[2], float2 (&bn)[2]) {
        int kcn = (kc + 1) & 31;
        const float2* sp = D1 + kcn*256;
        bn[0] = __ldg(sp + f1[0]);
        bn[1] = __ldg(sp + f1[1]);
        int k0 = kc*8;
        uint32_t a[2][4];
#pragma unroll
        for (int am = 0; am < 2; am++) {
            int row = mBase + am*16 + g;
            a[am][0] = __float_as_uint(zs[row*260 + k0 + t]);
            a[am][1] = __float_as_uint(zs[(row+8)*260 + k0 + t]);
            a[am][2] = __float_as_uint(zs[row*260 + k0 + t + 4]);
            a[am][3] = __float_as_uint(zs[(row+8)*260 + k0 + t + 4]);
        }
#pragma unroll
        for (int nt = 0; nt < 2; nt++) {
            uint32_t b0 = __float_as_uint(bc[nt].x);
            uint32_t b1 = __float_as_uint(bc[nt].y);
            mma_tf32(acc1[0][nt], a[0], b0, b1);
            mma_tf32(acc1[1][nt], a[1], b0, b1);
        }
    };
    // GEMM2 kstep: K=64 in 8 chunks; A from u, B from D2 (wraps mod 8)
    auto kstep2 = [&](int kc, float2 (&bc)[8], float2 (&bn)[8]) {
        int kcn = (kc + 1) & 7;
        const float2* sp = D2 + kcn*1024;
#pragma unroll
        for (int nt = 0; nt < 8; nt++) bn[nt] = __ldg(sp + f2[nt]);
        int k0 = kc*8;
        uint32_t a[2][4];
#pragma unroll
        for (int am = 0; am < 2; am++) {
            int row = mBase + am*16 + g;
            a[am][0] = __float_as_uint(u[row*68 + k0 + t]);
            a[am][1] = __float_as_uint(u[(row+8)*68 + k0 + t]);
            a[am][2] = __float_as_uint(u[row*68 + k0 + t + 4]);
            a[am][3] = __float_as_uint(u[(row+8)*68 + k0 + t + 4]);
        }
#pragma unroll
        for (int nt = 0; nt < 8; nt++) {
            uint32_t b0 = __float_as_uint(bc[nt].x);
            uint32_t b1 = __float_as_uint(bc[nt].y);
            mma_tf32(acc2[0][nt], a[0], b0, b1);
            mma_tf32(acc2[1][nt], a[1], b0, b1);
        }
    };

    for (int it = 0; it < iters; it++) {
        bool last = (it == iters - 1);

        // ---- GEMM1: u = z @ Dict^T ----
#pragma unroll
        for (int am = 0; am < 2; am++)
#pragma unroll
            for (int nt = 0; nt < 2; nt++)
#pragma unroll
                for (int j = 0; j < 4; j++) acc1[am][nt][j] = 0.f;

        for (int kc = 0; kc < 32; kc += 2) {
            kstep1(kc,     b1A, b1B);
            kstep1(kc + 1, b1B, b1A);
        }
        // store u (tf32-rounded) for GEMM2 A-frags
#pragma unroll
        for (int am = 0; am < 2; am++) {
#pragma unroll
            for (int nt = 0; nt < 2; nt++) {
                int row = mBase + am*16 + g;
                int col = wn*16 + nt*8 + 2*t;
                u[row*68 + col]       = __uint_as_float(f2tf32(acc1[am][nt][0]));
                u[row*68 + col + 1]   = __uint_as_float(f2tf32(acc1[am][nt][1]));
                u[(row+8)*68 + col]   = __uint_as_float(f2tf32(acc1[am][nt][2]));
                u[(row+8)*68 + col+1] = __uint_as_float(f2tf32(acc1[am][nt][3]));
            }
        }
        __syncthreads();   // u visible; zs reads (GEMM1) complete

        // ---- GEMM2: corr = u @ (Dict/L);  z = soft(z - corr + yl, lam) ----
#pragma unroll
        for (int am = 0; am < 2; am++)
#pragma unroll
            for (int nt = 0; nt < 8; nt++)
#pragma unroll
                for (int j = 0; j < 4; j++) acc2[am][nt][j] = 0.f;

        for (int kc = 0; kc < 8; kc += 2) {
            kstep2(kc,     b2A, b2B);
            kstep2(kc + 1, b2B, b2A);
        }

#pragma unroll
        for (int am = 0; am < 2; am++) {
#pragma unroll
            for (int nt = 0; nt < 8; nt++) {
                int row = mBase + am*16 + g;
                int col = nBase + nt*8 + 2*t;
                int i0 = row*260 + col;
                int i1 = (row+8)*260 + col;
                float z0 = softt(zs[i0]   - acc2[am][nt][0] + yl[i0],   lam[i0]);
                float z1 = softt(zs[i0+1] - acc2[am][nt][1] + yl[i0+1], lam[i0+1]);
                float z2 = softt(zs[i1]   - acc2[am][nt][2] + yl[i1],   lam[i1]);
                float z3 = softt(zs[i1+1] - acc2[am][nt][3] + yl[i1+1], lam[i1+1]);
                zs[i0]   = last ? z0 : __uint_as_float(f2tf32(z0));
                zs[i0+1] = last ? z1 : __uint_as_float(f2tf32(z1));
                zs[i1]   = last ? z2 : __uint_as_float(f2tf32(z2));
                zs[i1+1] = last ? z3 : __uint_as_float(f2tf32(z3));
            }
        }
        __syncthreads();   // zs writes visible before next GEMM1 / u rewrite
    }

    for (int i = tid; i < 16384; i += 256) {
        int n = i >> 6, p = i & 63;
        zOut[((size_t)(b*256 + n))*4096 + px0 + p] = zs[p*260 + n];
    }
    __syncthreads();

    float* dsh = smem + DSH_OFF;
    for (int i = tid; i < 16384; i += 256) {
        int c = i >> 8, a = i & 255;
        dsh[a*68 + c] = Dict[c*256 + a];
    }
    __syncthreads();

    {
        int p = tid & 63, cg = tid >> 6;
        float acc3[16];
#pragma unroll
        for (int j = 0; j < 16; j++) acc3[j] = 0.f;
        for (int a = 0; a < 256; a++) {
            float zv = zs[p*260 + a];
            const float4* dr = (const float4*)&dsh[a*68 + cg*16];
            float4 d0 = dr[0], d1 = dr[1], d2 = dr[2], d3 = dr[3];
            acc3[0]  += zv*d0.x; acc3[1]  += zv*d0.y; acc3[2]  += zv*d0.z; acc3[3]  += zv*d0.w;
            acc3[4]  += zv*d1.x; acc3[5]  += zv*d1.y; acc3[6]  += zv*d1.z; acc3[7]  += zv*d1.w;
            acc3[8]  += zv*d2.x; acc3[9]  += zv*d2.y; acc3[10] += zv*d2.z; acc3[11] += zv*d2.w;
            acc3[12] += zv*d3.x; acc3[13] += zv*d3.y; acc3[14] += zv*d3.z; acc3[15] += zv*d3.w;
        }
#pragma unroll
        for (int j = 0; j < 16; j++)
            xrOut[((size_t)(b*64 + cg*16 + j))*4096 + px0 + p] = acc3[j];
    }
}

// ---------------- launch ----------------------------------------------------
extern "C" void kernel_launch(void* const* d_in, const int* in_sizes, int n_in,
                              void* d_out, int out_size)
{
    const float* x      = (const float*)d_in[0];
    const float* conv_w = (const float*)d_in[1];
    const float* conv_b = (const float*)d_in[2];
    const float* r1w1   = (const float*)d_in[3];
    const float* r1w2   = (const float*)d_in[4];
    const float* r2w1   = (const float*)d_in[5];
    const float* r2w2   = (const float*)d_in[6];
    const float* caw1   = (const float*)d_in[7];
    const float* caw2   = (const float*)d_in[8];
    const float* saw    = (const float*)d_in[9];
    const float* Dict   = (const float*)d_in[10];
    const float* Lp     = (const float*)d_in[11];
    const int*   itp    = (const int*)d_in[12];

    float* out   = (float*)d_out;
    float* zOut  = out;
    float* xrOut = out + (size_t)8*256*4096;
    float* dOut  = xrOut + (size_t)8*64*4096;

    float *lp;
    uint32_t *xpk, *lpk, *tpk, *w3a, *w3b1, *w3b2, *w1a, *w1b;
    cudaGetSymbolAddress((void**)&lp,   g_l);
    cudaGetSymbolAddress((void**)&xpk,  g_xpk);
    cudaGetSymbolAddress((void**)&lpk,  g_lpk);
    cudaGetSymbolAddress((void**)&tpk,  g_tpk);
    cudaGetSymbolAddress((void**)&w3a,  g_w3a);
    cudaGetSymbolAddress((void**)&w3b1, g_w3b1);
    cudaGetSymbolAddress((void**)&w3b2, g_w3b2);
    cudaGetSymbolAddress((void**)&w1a,  g_w1a);
    cudaGetSymbolAddress((void**)&w1b,  g_w1b);

    cudaFuncSetAttribute((const void*)conv3x3_bf16<64, true, true>,
                         cudaFuncAttributeMaxDynamicSharedMemorySize, CONV3_SMEM);
    cudaFuncSetAttribute((const void*)conv3x3_bf16<256, false, false>,
                         cudaFuncAttributeMaxDynamicSharedMemorySize, CONV3_SMEM);
    cudaFuncSetAttribute((const void*)lista_kernel,
                         cudaFuncAttributeMaxDynamicSharedMemorySize, LISTA_SMEM);

    // Dict fragment tables + bf16 packing
    pack_D1_kernel<<<32, 256>>>(Dict);
    pack_D2_kernel<<<32, 256>>>(Dict, Lp);
    pack_pairs_kernel<<<4096, 256>>>(x, xpk, 8*32*4096);
    pack_w3_kernel<<<288, 256>>>(conv_w, w3a, 64, 256);
    pack_w3_kernel<<<576, 256>>>(r1w1, w3b1, 256, 128);
    pack_w3_kernel<<<576, 256>>>(r2w1, w3b2, 256, 128);
    pack_w1_kernel<<<64, 256>>>(r1w2, w1a);
    pack_w1_kernel<<<64, 256>>>(r2w2, w1b);

    // encoder
    conv3x3_bf16<64, true, true><<<dim3(128, 4), 256, CONV3_SMEM>>>(
        xpk, w3a, conv_b, lp, lpk, 256);

    conv3x3_bf16<256, false, false><<<dim3(128, 2), 256, CONV3_SMEM>>>(
        lpk, w3b1, nullptr, nullptr, tpk, 128);
    conv1x1_bf16<true><<<dim3(128, 4), 256>>>(tpk, w1a, lp, lpk);

    conv3x3_bf16<256, false, false><<<dim3(128, 2), 256, CONV3_SMEM>>>(
        lpk, w3b2, nullptr, nullptr, tpk, 128);
    conv1x1_bf16<false><<<dim3(128, 4), 256>>>(tpk, w1b, lp, nullptr);

    // CBAM attention
    pool_kernel<<<2048, 256>>>();
    camlp_kernel<<<8, 256>>>(caw1, caw2);
    spatial_stats_kernel<<<128, 256>>>();
    saconv_kernel<<<128, 256>>>(saw);

    // LISTA (rank-64 factorized)
    lista_kernel<<<512, 256, LISTA_SMEM>>>(x, Dict, Lp, itp, zOut, xrOut);

    cudaMemcpyAsync(dOut, Dict, (size_t)64*256*sizeof(float), cudaMemcpyDeviceToDevice);
}